// round 13
// baseline (speedup 1.0000x reference)
#include <cuda_runtime.h>
#include <cuda_bf16.h>
#include <math.h>
#include <stdint.h>

#define TT 64
#define BSZ 128
#define HD 512
#define NLA 15
#define BH (BSZ*HD)
#define HH (HD*HD)
#define NWL (3L*5*4*512*512)
#define NWG (5L*3*3*512*512)

__device__ float g_c[2][NLA][BH];
__device__ float g_tp[30][BH];
__device__ float g_slp[5][BH];
__device__ volatile unsigned g_bar;

__device__ __nv_bfloat16 g_Wxhi[NWL], g_Wxlo[NWL], g_Whhi[NWL], g_Whlo[NWL];
__device__ __nv_bfloat16 g_Wghh[NWG], g_Wghl[NWG], g_Wgph[NWG], g_Wgpl[NWG];
__device__ __nv_bfloat16 g_Wthi[15L*HH], g_Wtlo[15L*HH];
__device__ __nv_bfloat16 g_xh[(long)TT*BH], g_xl[(long)TT*BH];
__device__ __nv_bfloat16 g_hbh[2][NLA][BH], g_hbl[2][NLA][BH];
__device__ __nv_bfloat16 g_hgh[2][BH], g_hgl[2][BH];
__device__ __nv_bfloat16 g_ichi[NLA][BH], g_iclo[NLA][BH];
__device__ __nv_bfloat16 g_cchi[NLA][BH], g_cclo[NLA][BH];

__device__ __forceinline__ float sigf(float x){ return 1.0f/(1.0f+expf(-x)); }

__global__ void zero_kernel(float* c0, __nv_bfloat16* hbh0, __nv_bfloat16* hbl0,
                            __nv_bfloat16* hgh0, __nv_bfloat16* hgl0){
    int n = NLA*BH;
    __nv_bfloat16 z = __float2bfloat16(0.f);
    for (int i = blockIdx.x*blockDim.x+threadIdx.x; i < n; i += gridDim.x*blockDim.x){
        c0[i]=0.f; hbh0[i]=z; hbl0[i]=z;
        if (i<BH){ hgh0[i]=z; hgl0[i]=z; }
    }
}

__global__ void conv_w_lstm(const float* __restrict__ Wx, const float* __restrict__ Wh,
    __nv_bfloat16* xh, __nv_bfloat16* xl, __nv_bfloat16* hh, __nv_bfloat16* hl){
    for (long i = (long)blockIdx.x*blockDim.x+threadIdx.x; i < NWL;
         i += (long)gridDim.x*blockDim.x){
        float w = Wx[i];
        __nv_bfloat16 hi = __float2bfloat16(w);
        xh[i] = hi; xl[i] = __float2bfloat16(w - __bfloat162float(hi));
        w = Wh[i];
        hi = __float2bfloat16(w);
        hh[i] = hi; hl[i] = __float2bfloat16(w - __bfloat162float(hi));
    }
}

__global__ void conv_wg(const float* __restrict__ Gh, const float* __restrict__ Gp,
    __nv_bfloat16* ghh, __nv_bfloat16* ghl, __nv_bfloat16* gph, __nv_bfloat16* gpl){
    for (long i = (long)blockIdx.x*blockDim.x+threadIdx.x; i < NWG;
         i += (long)gridDim.x*blockDim.x){
        float w = Gh[i];
        __nv_bfloat16 hi = __float2bfloat16(w);
        ghh[i] = hi; ghl[i] = __float2bfloat16(w - __bfloat162float(hi));
        w = Gp[i];
        hi = __float2bfloat16(w);
        gph[i] = hi; gpl[i] = __float2bfloat16(w - __bfloat162float(hi));
    }
}

__global__ void conv_wilc(const float* __restrict__ W,
                          __nv_bfloat16* th, __nv_bfloat16* tl){
    int zb = blockIdx.z;
    int z0 = blockIdx.y*32, y0 = blockIdx.x*32;
    __shared__ float s[32][33];
    int tx = threadIdx.x&31, ty = threadIdx.x>>5;
    const float* Wb = W + (long)zb*HH;
#pragma unroll
    for (int r=0;r<4;r++)
        s[ty+r*8][tx] = Wb[(long)(z0+ty+r*8)*512 + y0+tx];
    __syncthreads();
#pragma unroll
    for (int r=0;r<4;r++){
        float w = s[tx][ty+r*8];
        __nv_bfloat16 hi = __float2bfloat16(w);
        long o = (long)zb*HH + (long)(y0+ty+r*8)*512 + z0+tx;
        th[o]=hi; tl[o]=__float2bfloat16(w - __bfloat162float(hi));
    }
}

__global__ void conv_x(const float* __restrict__ x, __nv_bfloat16* xh, __nv_bfloat16* xl){
    const long N = (long)TT*BH;
    for (long i = (long)blockIdx.x*blockDim.x+threadIdx.x; i < N;
         i += (long)gridDim.x*blockDim.x){
        float w = x[i];
        __nv_bfloat16 hi = __float2bfloat16(w);
        xh[i] = hi; xl[i] = __float2bfloat16(w - __bfloat162float(hi));
    }
}

__device__ __forceinline__ void ldsm4(uint32_t addr, uint32_t &r0, uint32_t &r1,
                                      uint32_t &r2, uint32_t &r3){
    asm volatile("ldmatrix.sync.aligned.m8n8.x4.shared.b16 {%0,%1,%2,%3}, [%4];"
        : "=r"(r0),"=r"(r1),"=r"(r2),"=r"(r3) : "r"(addr));
}
__device__ __forceinline__ void mma16816(float* c, const uint32_t* a,
                                         uint32_t b0, uint32_t b1){
    asm volatile("mma.sync.aligned.m16n8k16.row.col.f32.bf16.bf16.f32 "
        "{%0,%1,%2,%3},{%4,%5,%6,%7},{%8,%9},{%0,%1,%2,%3};"
        : "+f"(c[0]),"+f"(c[1]),"+f"(c[2]),"+f"(c[3])
        : "r"(a[0]),"r"(a[1]),"r"(a[2]),"r"(a[3]),"r"(b0),"r"(b1));
}
__device__ __forceinline__ void cpa16(uint32_t dst, const void* src){
    asm volatile("cp.async.ca.shared.global [%0], [%1], 16;" :: "r"(dst), "l"(src));
}
// cp.async with L2 cache-policy hint
__device__ __forceinline__ void cpa16_p(uint32_t dst, const void* src,
                                        unsigned long long pol){
    asm volatile("cp.async.ca.shared.global.L2::cache_hint [%0], [%1], 16, %2;"
        :: "r"(dst), "l"(src), "l"(pol));
}
__device__ __forceinline__ unsigned long long pol_last(){
    unsigned long long p;
    asm("createpolicy.fractional.L2::evict_last.b64 %0, 1.0;" : "=l"(p));
    return p;
}
__device__ __forceinline__ unsigned long long pol_first(){
    unsigned long long p;
    asm("createpolicy.fractional.L2::evict_first.b64 %0, 1.0;" : "=l"(p));
    return p;
}
__device__ __forceinline__ void cpa_commit(){ asm volatile("cp.async.commit_group;"); }

__device__ __forceinline__ void grid_barrier(unsigned nblocks){
    __syncthreads();
    __threadfence();
    if (threadIdx.x == 0){
        unsigned token = atomicAdd((unsigned*)&g_bar, 1u);
        unsigned target = (token/nblocks + 1u)*nblocks;
        while (g_bar < target) { }
    }
    __syncthreads();
}

// ---- fused 5-level LSTM: persistent, weights streamed with evict_first -------
__global__ __launch_bounds__(128,3) void lstm5_mma(
    const __nv_bfloat16* __restrict__ xh_t, const __nv_bfloat16* __restrict__ xl_t,
    const __nv_bfloat16* __restrict__ hbhp, const __nv_bfloat16* __restrict__ hblp,
    __nv_bfloat16* __restrict__ hbhq, __nv_bfloat16* __restrict__ hblq,
    const __nv_bfloat16* __restrict__ wxh, const __nv_bfloat16* __restrict__ wxl,
    const __nv_bfloat16* __restrict__ whh, const __nv_bfloat16* __restrict__ whl,
    const float* __restrict__ bl, const float* __restrict__ cpb,
    float* __restrict__ cqb)
{
    const int a = blockIdx.z;
    const int m0 = blockIdx.y*32, n0 = blockIdx.x*16;
    const int tid = threadIdx.x, lane = tid&31, g = tid>>5;
    const unsigned long long PF = pol_first();

    __shared__ __align__(16) __nv_bfloat16 sA[3][2][32][40];
    __shared__ __align__(16) __nv_bfloat16 sW[3][2][4][16][40];

    const uint32_t sA_base = (uint32_t)__cvta_generic_to_shared(&sA[0][0][0][0]);
    const uint32_t sW_base = (uint32_t)__cvta_generic_to_shared(&sW[0][0][0][0][0]);

    const int a_row = lane&15, a_ko = (lane>>4)*8;
    const int b_r = lane&7, b_sel = lane>>3;
    const int b_rowoff = b_r + ((b_sel>>1)?8:0), b_ko = (b_sel&1)*8;

    for (int l=0; l<5; l++){
        const __nv_bfloat16* Ah_[2];
        const __nv_bfloat16* Al_[2];
        if (l==0){ Ah_[0] = xh_t; Al_[0] = xl_t; }
        else { Ah_[0] = hbhq + (long)((l-1)*3+a)*BH; Al_[0] = hblq + (long)((l-1)*3+a)*BH; }
        Ah_[1] = hbhp + (long)(l*3+a)*BH;
        Al_[1] = hblp + (long)(l*3+a)*BH;
        const __nv_bfloat16* Wp[2][2] = {
            {wxh + (long)(a*20+l*4)*HH, wxl + (long)(a*20+l*4)*HH},
            {whh + (long)(a*20+l*4)*HH, whl + (long)(a*20+l*4)*HH}};

        float C[2][2][4];
#pragma unroll
        for (int mh=0;mh<2;mh++)
#pragma unroll
            for (int f=0;f<2;f++)
#pragma unroll
                for (int r=0;r<4;r++) C[mh][f][r]=0.f;

        auto prefetch = [&](int kc2){
            int st = kc2 % 3, s = kc2>>4, k0 = (kc2&15)*32;
#pragma unroll
            for (int it=0; it<2; it++){
                int idx = tid + it*128;
                int q = idx&3, row = (idx>>2)&31, hl = (idx>>7)&1;
                const __nv_bfloat16* src = (hl ? Al_[s] : Ah_[s]) + (long)(m0+row)*512 + k0 + q*8;
                cpa16(sA_base + (uint32_t)((((st*2+hl)*32 + row)*40 + q*8)*2), src);
            }
#pragma unroll
            for (int it=0; it<4; it++){
                int idx = tid + it*128;
                int q = idx&3, n = (idx>>2)&15, gg = (idx>>6)&3, hl = (idx>>8)&1;
                const __nv_bfloat16* src = Wp[s][hl] + (long)gg*HH + (long)(n0+n)*512 + k0 + q*8;
                cpa16_p(sW_base + (uint32_t)(((((st*2+hl)*4+gg)*16 + n)*40 + q*8)*2), src, PF);
            }
            cpa_commit();
        };

        prefetch(0); prefetch(1);
        for (int kc2=0; kc2<32; kc2++){
            const int st = kc2 % 3;
            if (kc2+2 < 32){
                prefetch(kc2+2);
                asm volatile("cp.async.wait_group 2;");
            } else if (kc2+1 < 32){
                asm volatile("cp.async.wait_group 1;");
            } else {
                asm volatile("cp.async.wait_group 0;");
            }
            __syncthreads();
#pragma unroll
            for (int kf=0;kf<2;kf++){
                uint32_t ah[2][4], al[2][4];
#pragma unroll
                for (int mh=0;mh<2;mh++){
                    uint32_t ad = sA_base + (uint32_t)(((((st*2+0)*32) + mh*16 + a_row)*40 + kf*16 + a_ko)*2);
                    ldsm4(ad, ah[mh][0], ah[mh][1], ah[mh][2], ah[mh][3]);
                    ad = sA_base + (uint32_t)(((((st*2+1)*32) + mh*16 + a_row)*40 + kf*16 + a_ko)*2);
                    ldsm4(ad, al[mh][0], al[mh][1], al[mh][2], al[mh][3]);
                }
                uint32_t bh0,bh1,bh2,bh3, bl0,bl1,bl2,bl3;
                {
                    uint32_t bd = sW_base + (uint32_t)(((((st*2+0)*4+g)*16 + b_rowoff)*40 + kf*16 + b_ko)*2);
                    ldsm4(bd, bh0,bh1,bh2,bh3);
                    bd = sW_base + (uint32_t)(((((st*2+1)*4+g)*16 + b_rowoff)*40 + kf*16 + b_ko)*2);
                    ldsm4(bd, bl0,bl1,bl2,bl3);
                }
#pragma unroll
                for (int mh=0;mh<2;mh++){
                    mma16816(C[mh][0], ah[mh], bh0, bh1);
                    mma16816(C[mh][1], ah[mh], bh2, bh3);
                    mma16816(C[mh][0], ah[mh], bl0, bl1);
                    mma16816(C[mh][1], ah[mh], bl2, bl3);
                    mma16816(C[mh][0], al[mh], bh0, bh1);
                    mma16816(C[mh][1], al[mh], bh2, bh3);
                }
            }
            __syncthreads();
        }

        float* preS = (float*)&sW[0][0][0][0][0];
        {
            int r = lane>>2, i2 = (lane&3)*2;
#pragma unroll
            for (int mh=0;mh<2;mh++)
#pragma unroll
                for (int f=0;f<2;f++){
                    int col = f*8 + i2;
                    preS[(g*32 + mh*16 + r)*16 + col]     = C[mh][f][0];
                    preS[(g*32 + mh*16 + r)*16 + col+1]   = C[mh][f][1];
                    preS[(g*32 + mh*16 + r+8)*16 + col]   = C[mh][f][2];
                    preS[(g*32 + mh*16 + r+8)*16 + col+1] = C[mh][f][3];
                }
        }
        __syncthreads();
        {
            const float* cp = cpb + (long)(l*3+a)*BH;
            float* cq = cqb + (long)(l*3+a)*BH;
            __nv_bfloat16* hh_out = hbhq + (long)(l*3+a)*BH;
            __nv_bfloat16* hl_out = hblq + (long)(l*3+a)*BH;
            for (int cell = tid; cell < 512; cell += 128){
                int m = cell>>4, n = cell&15;
                int gn = n0 + n;
                float p[4];
#pragma unroll
                for (int gg=0;gg<4;gg++)
                    p[gg] = preS[(gg*32+m)*16 + n] + bl[((long)(a*5+l)*4+gg)*512 + gn];
                long o = (long)(m0+m)*512 + gn;
                float cn = sigf(p[1])*cp[o] + sigf(p[0])*tanhf(p[2]);
                float hv = sigf(p[3])*tanhf(cn);
                cq[o] = cn;
                __nv_bfloat16 hh = __float2bfloat16(hv);
                hh_out[o] = hh;
                hl_out[o] = __float2bfloat16(hv - __bfloat162float(hh));
            }
        }
        if (l < 4) grid_barrier(384u);
    }
}

// ---- single-level LSTM fallback ----------------------------------------------
__global__ __launch_bounds__(128) void lstm_mma(
    const __nv_bfloat16* __restrict__ A1h, const __nv_bfloat16* __restrict__ A1l, long a1zs,
    const __nv_bfloat16* __restrict__ A2h, const __nv_bfloat16* __restrict__ A2l,
    const __nv_bfloat16* __restrict__ W1h, const __nv_bfloat16* __restrict__ W1l,
    const __nv_bfloat16* __restrict__ W2h, const __nv_bfloat16* __restrict__ W2l,
    const float* __restrict__ bl, int l, const float* __restrict__ cpb,
    float* __restrict__ cqb,
    __nv_bfloat16* __restrict__ hbhq, __nv_bfloat16* __restrict__ hblq)
{
    const int a = blockIdx.z;
    const int m0 = blockIdx.y*32, n0 = blockIdx.x*16;
    const int tid = threadIdx.x, lane = tid&31, g = tid>>5;
    const unsigned long long PF = pol_first();

    __shared__ __align__(16) __nv_bfloat16 sA[3][2][32][40];
    __shared__ __align__(16) __nv_bfloat16 sW[3][2][4][16][40];

    float C[2][2][4];
#pragma unroll
    for (int mh=0;mh<2;mh++)
#pragma unroll
        for (int f=0;f<2;f++)
#pragma unroll
            for (int r=0;r<4;r++) C[mh][f][r]=0.f;

    const __nv_bfloat16* Ah_[2] = {A1h + (long)a*a1zs, A2h + (long)a*BH};
    const __nv_bfloat16* Al_[2] = {A1l + (long)a*a1zs, A2l + (long)a*BH};
    const __nv_bfloat16* Wp[2][2] = {
        {W1h + (long)a*20*HH, W1l + (long)a*20*HH},
        {W2h + (long)a*20*HH, W2l + (long)a*20*HH}};

    const uint32_t sA_base = (uint32_t)__cvta_generic_to_shared(&sA[0][0][0][0]);
    const uint32_t sW_base = (uint32_t)__cvta_generic_to_shared(&sW[0][0][0][0][0]);

    const int a_row = lane&15, a_ko = (lane>>4)*8;
    const int b_r = lane&7, b_sel = lane>>3;
    const int b_rowoff = b_r + ((b_sel>>1)?8:0), b_ko = (b_sel&1)*8;

    auto prefetch = [&](int kc2){
        int st = kc2 % 3, s = kc2>>4, k0 = (kc2&15)*32;
#pragma unroll
        for (int it=0; it<2; it++){
            int idx = tid + it*128;
            int q = idx&3, row = (idx>>2)&31, hl = (idx>>7)&1;
            const __nv_bfloat16* src = (hl ? Al_[s] : Ah_[s]) + (long)(m0+row)*512 + k0 + q*8;
            cpa16(sA_base + (uint32_t)((((st*2+hl)*32 + row)*40 + q*8)*2), src);
        }
#pragma unroll
        for (int it=0; it<4; it++){
            int idx = tid + it*128;
            int q = idx&3, n = (idx>>2)&15, gg = (idx>>6)&3, hl = (idx>>8)&1;
            const __nv_bfloat16* src = Wp[s][hl] + (long)gg*HH + (long)(n0+n)*512 + k0 + q*8;
            cpa16_p(sW_base + (uint32_t)(((((st*2+hl)*4+gg)*16 + n)*40 + q*8)*2), src, PF);
        }
        cpa_commit();
    };

    prefetch(0); prefetch(1);
    for (int kc2=0; kc2<32; kc2++){
        const int st = kc2 % 3;
        if (kc2+2 < 32){
            prefetch(kc2+2);
            asm volatile("cp.async.wait_group 2;");
        } else if (kc2+1 < 32){
            asm volatile("cp.async.wait_group 1;");
        } else {
            asm volatile("cp.async.wait_group 0;");
        }
        __syncthreads();
#pragma unroll
        for (int kf=0;kf<2;kf++){
            uint32_t ah[2][4], al[2][4];
#pragma unroll
            for (int mh=0;mh<2;mh++){
                uint32_t ad = sA_base + (uint32_t)(((((st*2+0)*32) + mh*16 + a_row)*40 + kf*16 + a_ko)*2);
                ldsm4(ad, ah[mh][0], ah[mh][1], ah[mh][2], ah[mh][3]);
                ad = sA_base + (uint32_t)(((((st*2+1)*32) + mh*16 + a_row)*40 + kf*16 + a_ko)*2);
                ldsm4(ad, al[mh][0], al[mh][1], al[mh][2], al[mh][3]);
            }
            uint32_t bh0,bh1,bh2,bh3, bl0,bl1,bl2,bl3;
            {
                uint32_t bd = sW_base + (uint32_t)(((((st*2+0)*4+g)*16 + b_rowoff)*40 + kf*16 + b_ko)*2);
                ldsm4(bd, bh0,bh1,bh2,bh3);
                bd = sW_base + (uint32_t)(((((st*2+1)*4+g)*16 + b_rowoff)*40 + kf*16 + b_ko)*2);
                ldsm4(bd, bl0,bl1,bl2,bl3);
            }
#pragma unroll
            for (int mh=0;mh<2;mh++){
                mma16816(C[mh][0], ah[mh], bh0, bh1);
                mma16816(C[mh][1], ah[mh], bh2, bh3);
                mma16816(C[mh][0], ah[mh], bl0, bl1);
                mma16816(C[mh][1], ah[mh], bl2, bl3);
                mma16816(C[mh][0], al[mh], bh0, bh1);
                mma16816(C[mh][1], al[mh], bh2, bh3);
            }
        }
        __syncthreads();
    }

    float* preS = (float*)&sW[0][0][0][0][0];
    {
        int r = lane>>2, i2 = (lane&3)*2;
#pragma unroll
        for (int mh=0;mh<2;mh++)
#pragma unroll
            for (int f=0;f<2;f++){
                int col = f*8 + i2;
                preS[(g*32 + mh*16 + r)*16 + col]     = C[mh][f][0];
                preS[(g*32 + mh*16 + r)*16 + col+1]   = C[mh][f][1];
                preS[(g*32 + mh*16 + r+8)*16 + col]   = C[mh][f][2];
                preS[(g*32 + mh*16 + r+8)*16 + col+1] = C[mh][f][3];
            }
    }
    __syncthreads();
    {
        const float* cp = cpb + (long)a*BH;
        for (int cell = tid; cell < 512; cell += 128){
            int m = cell>>4, n = cell&15;
            int gn = n0 + n;
            float p[4];
#pragma unroll
            for (int gg=0;gg<4;gg++)
                p[gg] = preS[(gg*32+m)*16 + n] + bl[((long)(a*5+l)*4+gg)*512 + gn];
            long o = (long)a*BH + (long)(m0+m)*512 + gn;
            float cn = sigf(p[1])*cp[(long)(m0+m)*512+gn] + sigf(p[0])*tanhf(p[2]);
            float hv = sigf(p[3])*tanhf(cn);
            cqb[o] = cn;
            __nv_bfloat16 hh = __float2bfloat16(hv);
            hbhq[o] = hh;
            hblq[o] = __float2bfloat16(hv - __bfloat162float(hh));
        }
    }
}

// ---- cell block: weights pinned L2 evict_last --------------------------------
__global__ __launch_bounds__(192) void cell_mma(
    const __nv_bfloat16* __restrict__ Hgh, const __nv_bfloat16* __restrict__ Hgl,
    const __nv_bfloat16* __restrict__ Hbh, const __nv_bfloat16* __restrict__ Hbl,
    const __nv_bfloat16* __restrict__ Ghh, const __nv_bfloat16* __restrict__ Ghl,
    const __nv_bfloat16* __restrict__ Gph, const __nv_bfloat16* __restrict__ Gpl,
    const float* __restrict__ bg, const float* __restrict__ scb,
    __nv_bfloat16* __restrict__ ichi, __nv_bfloat16* __restrict__ iclo,
    __nv_bfloat16* __restrict__ cchi, __nv_bfloat16* __restrict__ cclo)
{
    const int zb = blockIdx.z;
    const int m0 = blockIdx.y*32, n0 = blockIdx.x*32;
    const int tid = threadIdx.x, lane = tid&31, wid = tid>>5;
    const int g = wid>>1, nb = (wid&1)*16;
    const unsigned long long PL = pol_last();

    __shared__ __align__(16) __nv_bfloat16 sA[2][2][32][40];
    __shared__ __align__(16) __nv_bfloat16 sW[2][2][3][32][40];

    float C[2][2][4];
#pragma unroll
    for (int mh=0;mh<2;mh++)
#pragma unroll
        for (int f=0;f<2;f++)
#pragma unroll
            for (int r=0;r<4;r++) C[mh][f][r]=0.f;

    const __nv_bfloat16* Ah_[2] = {Hgh, Hbh + (long)zb*BH};
    const __nv_bfloat16* Al_[2] = {Hgl, Hbl + (long)zb*BH};
    const __nv_bfloat16* Wp[2][2] = {
        {Ghh + (long)zb*3*HH, Ghl + (long)zb*3*HH},
        {Gph + (long)zb*3*HH, Gpl + (long)zb*3*HH}};

    const uint32_t sA_base = (uint32_t)__cvta_generic_to_shared(&sA[0][0][0][0]);
    const uint32_t sW_base = (uint32_t)__cvta_generic_to_shared(&sW[0][0][0][0][0]);

    const int a_row = lane&15, a_ko = (lane>>4)*8;
    const int b_r = lane&7, b_sel = lane>>3;
    const int b_rowoff = b_r + ((b_sel>>1)?8:0), b_ko = (b_sel&1)*8;

    auto prefetch = [&](int kc2){
        int st = kc2&1, s = kc2>>4, k0 = (kc2&15)*32;
#pragma unroll
        for (int it=0; it<2; it++){
            int idx = tid + it*192;
            if (idx < 256){
                int hl = idx>>7, lm = (idx>>2)&31, lq = idx&3;
                const __nv_bfloat16* src = (hl ? Al_[s] : Ah_[s]) + (long)(m0+lm)*512 + k0 + lq*8;
                cpa16(sA_base + (uint32_t)((((st*2+hl)*32 + lm)*40 + lq*8)*2), src);
            }
        }
#pragma unroll
        for (int it=0; it<4; it++){
            int idx = tid + it*192;
            int q = idx&3, n = (idx>>2)&31, rest = idx>>7;
            int gg = rest % 3, hl = rest / 3;
            const __nv_bfloat16* src = Wp[s][hl] + (long)gg*HH + (long)(n0+n)*512 + k0 + q*8;
            cpa16_p(sW_base + (uint32_t)(((((st*2+hl)*3+gg)*32 + n)*40 + q*8)*2), src, PL);
        }
        cpa_commit();
    };

    prefetch(0);
    for (int kc2=0; kc2<32; kc2++){
        const int st = kc2&1;
        if (kc2+1 < 32){
            prefetch(kc2+1);
            asm volatile("cp.async.wait_group 1;");
        } else {
            asm volatile("cp.async.wait_group 0;");
        }
        __syncthreads();
#pragma unroll
        for (int kf=0;kf<2;kf++){
            uint32_t ah[2][4], al[2][4];
#pragma unroll
            for (int mh=0;mh<2;mh++){
                uint32_t ad = sA_base + (uint32_t)(((((st*2+0)*32) + mh*16 + a_row)*40 + kf*16 + a_ko)*2);
                ldsm4(ad, ah[mh][0], ah[mh][1], ah[mh][2], ah[mh][3]);
                ad = sA_base + (uint32_t)(((((st*2+1)*32) + mh*16 + a_row)*40 + kf*16 + a_ko)*2);
                ldsm4(ad, al[mh][0], al[mh][1], al[mh][2], al[mh][3]);
            }
            uint32_t bh0,bh1,bh2,bh3, bl0,bl1,bl2,bl3;
            {
                uint32_t bd = sW_base + (uint32_t)((((((st*2+0)*3)+g)*32 + nb + b_rowoff)*40 + kf*16 + b_ko)*2);
                ldsm4(bd, bh0,bh1,bh2,bh3);
                bd = sW_base + (uint32_t)((((((st*2+1)*3)+g)*32 + nb + b_rowoff)*40 + kf*16 + b_ko)*2);
                ldsm4(bd, bl0,bl1,bl2,bl3);
            }
#pragma unroll
            for (int mh=0;mh<2;mh++){
                mma16816(C[mh][0], ah[mh], bh0, bh1);
                mma16816(C[mh][1], ah[mh], bh2, bh3);
                mma16816(C[mh][0], ah[mh], bl0, bl1);
                mma16816(C[mh][1], ah[mh], bl2, bl3);
                mma16816(C[mh][0], al[mh], bh0, bh1);
                mma16816(C[mh][1], al[mh], bh2, bh3);
            }
        }
        __syncthreads();
    }

    float* preS = (float*)&sW[0][0][0][0][0];
    {
        int r = lane>>2, i2 = (lane&3)*2;
#pragma unroll
        for (int mh=0;mh<2;mh++)
#pragma unroll
            for (int f=0;f<2;f++){
                int col = nb + f*8 + i2;
                preS[(g*32 + mh*16 + r)*32 + col]     = C[mh][f][0];
                preS[(g*32 + mh*16 + r)*32 + col+1]   = C[mh][f][1];
                preS[(g*32 + mh*16 + r+8)*32 + col]   = C[mh][f][2];
                preS[(g*32 + mh*16 + r+8)*32 + col+1] = C[mh][f][3];
            }
    }
    __syncthreads();
    {
        const float* sc = scb + (long)zb*BH;
        for (int cell = tid; cell < 1024; cell += 192){
            int m = cell>>5, n = cell&31;
            int gn = n0 + n;
            float p[3];
#pragma unroll
            for (int gg=0;gg<3;gg++)
                p[gg] = preS[(gg*32+m)*32 + n] + bg[((long)zb*3+gg)*512 + gn];
            long r = (long)(m0+m)*512 + gn;
            float icv = sigf(p[0]) * sc[r];
            float ccv = sigf(p[1])*tanhf(p[2]) + icv;
            long o = (long)zb*BH + r;
            __nv_bfloat16 ih = __float2bfloat16(icv);
            ichi[o] = ih; iclo[o] = __float2bfloat16(icv - __bfloat162float(ih));
            __nv_bfloat16 ch = __float2bfloat16(ccv);
            cchi[o] = ch; cclo[o] = __float2bfloat16(ccv - __bfloat162float(ch));
        }
    }
}

// ---- t12: weights pinned L2 evict_last ---------------------------------------
__global__ __launch_bounds__(128) void t12_mma(
    const __nv_bfloat16* __restrict__ ichi, const __nv_bfloat16* __restrict__ iclo,
    const __nv_bfloat16* __restrict__ cchi, const __nv_bfloat16* __restrict__ cclo,
    const __nv_bfloat16* __restrict__ Wth, const __nv_bfloat16* __restrict__ Wtl,
    float* __restrict__ tp)
{
    const int zb = blockIdx.z;
    const int l = zb/3, a = zb%3;
    const int m0 = blockIdx.y*32, n0 = blockIdx.x*32;
    const int tid = threadIdx.x, lane = tid&31, wid = tid>>5;
    const int s = wid>>1, nb = (wid&1)*16;
    const unsigned long long PL = pol_last();

    __shared__ __align__(16) __nv_bfloat16 sA[2][2][2][32][40];
    __shared__ __align__(16) __nv_bfloat16 sW[2][2][32][40];

    float C[2][2][4];
#pragma unroll
    for (int mh=0;mh<2;mh++)
#pragma unroll
        for (int f=0;f<2;f++)
#pragma unroll
            for (int r=0;r<4;r++) C[mh][f][r]=0.f;

    const __nv_bfloat16* Asrc[2][2] = {
        {ichi + (long)zb*BH, iclo + (long)zb*BH},
        {cchi + (long)zb*BH, cclo + (long)zb*BH}};
    const __nv_bfloat16* Wsrc[2] = {Wth + (long)zb*HH, Wtl + (long)zb*HH};

    const uint32_t sA_base = (uint32_t)__cvta_generic_to_shared(&sA[0][0][0][0][0]);
    const uint32_t sW_base = (uint32_t)__cvta_generic_to_shared(&sW[0][0][0][0]);

    const int a_row = lane&15, a_ko = (lane>>4)*8;
    const int b_r = lane&7, b_sel = lane>>3;
    const int b_rowoff = b_r + ((b_sel>>1)?8:0), b_ko = (b_sel&1)*8;

    auto prefetch = [&](int kc){
        int st = kc&1, k0 = kc*32;
#pragma unroll
        for (int it=0; it<4; it++){
            int idx = tid + it*128;
            int q = idx&3, row = (idx>>2)&31, hl = (idx>>7)&1, ss = (idx>>8)&1;
            const __nv_bfloat16* src = Asrc[ss][hl] + (long)(m0+row)*512 + k0 + q*8;
            cpa16(sA_base + (uint32_t)(((((st*2+ss)*2+hl)*32 + row)*40 + q*8)*2), src);
        }
#pragma unroll
        for (int it=0; it<2; it++){
            int idx = tid + it*128;
            int q = idx&3, row = (idx>>2)&31, hl = (idx>>7)&1;
            const __nv_bfloat16* src = Wsrc[hl] + (long)(n0+row)*512 + k0 + q*8;
            cpa16_p(sW_base + (uint32_t)((((st*2+hl)*32 + row)*40 + q*8)*2), src, PL);
        }
        cpa_commit();
    };

    prefetch(0);
    for (int kc=0; kc<16; kc++){
        const int st = kc&1;
        if (kc+1 < 16){
            prefetch(kc+1);
            asm volatile("cp.async.wait_group 1;");
        } else {
            asm volatile("cp.async.wait_group 0;");
        }
        __syncthreads();
#pragma unroll
        for (int kf=0;kf<2;kf++){
            uint32_t ah[2][4], al[2][4];
#pragma unroll
            for (int mh=0;mh<2;mh++){
                uint32_t ad = sA_base + (uint32_t)((((((st*2+s)*2+0)*32) + mh*16 + a_row)*40 + kf*16 + a_ko)*2);
                ldsm4(ad, ah[mh][0], ah[mh][1], ah[mh][2], ah[mh][3]);
                ad = sA_base + (uint32_t)((((((st*2+s)*2+1)*32) + mh*16 + a_row)*40 + kf*16 + a_ko)*2);
                ldsm4(ad, al[mh][0], al[mh][1], al[mh][2], al[mh][3]);
            }
            uint32_t bh0,bh1,bh2,bh3, bl0,bl1,bl2,bl3;
            {
                uint32_t bd = sW_base + (uint32_t)((((st*2+0)*32 + nb + b_rowoff)*40 + kf*16 + b_ko)*2);
                ldsm4(bd, bh0,bh1,bh2,bh3);
                bd = sW_base + (uint32_t)((((st*2+1)*32 + nb + b_rowoff)*40 + kf*16 + b_ko)*2);
                ldsm4(bd, bl0,bl1,bl2,bl3);
            }
#pragma unroll
            for (int mh=0;mh<2;mh++){
                mma16816(C[mh][0], ah[mh], bh0, bh1);
                mma16816(C[mh][1], ah[mh], bh2, bh3);
                mma16816(C[mh][0], ah[mh], bl0, bl1);
                mma16816(C[mh][1], ah[mh], bl2, bl3);
                mma16816(C[mh][0], al[mh], bh0, bh1);
                mma16816(C[mh][1], al[mh], bh2, bh3);
            }
        }
        __syncthreads();
    }

    float* tpo = tp + ((long)((2*l+s)*3+a))*BH;
    {
        int r = lane>>2, i2 = (lane&3)*2;
#pragma unroll
        for (int mh=0;mh<2;mh++)
#pragma unroll
            for (int f=0;f<2;f++){
                int row = m0 + mh*16 + r;
                int col = n0 + nb + f*8 + i2;
                tpo[(long)row*512 + col]       = C[mh][f][0];
                tpo[(long)row*512 + col+1]     = C[mh][f][1];
                tpo[(long)(row+8)*512 + col]   = C[mh][f][2];
                tpo[(long)(row+8)*512 + col+1] = C[mh][f][3];
            }
    }
}

// ---- fused comb + single_li (Wsl loads hinted evict_last) --------------------
__global__ __launch_bounds__(128) void combsl(
    const float* __restrict__ tp, const float* __restrict__ bilc,
    const float* __restrict__ Wsl, float* __restrict__ part)
{
    const int l = blockIdx.z, m0 = blockIdx.y*16, n0 = blockIdx.x*64;
    __shared__ __align__(16) float s1[16][520];
    __shared__ __align__(16) float Ws[16][68];
    const int tid = threadIdx.x;
    const int row = tid>>3, ln = tid&7;
    const int b = m0 + row;
    const unsigned long long PL = pol_last();

    float mx = -1e30f;
    for (int i=0;i<64;i++){
        int z = ln + i*8;
        float v1 = bilc[(long)(l*3+0)*512+z] + bilc[(long)(l*3+1)*512+z] + bilc[(long)(l*3+2)*512+z];
#pragma unroll
        for (int a=0;a<3;a++)
            v1 += tp[((long)((2*l+0)*3+a))*BH + (long)b*512 + z];
        s1[row][z] = v1;
        mx = fmaxf(mx, v1);
    }
#pragma unroll
    for (int o=4;o>0;o>>=1) mx = fmaxf(mx, __shfl_xor_sync(0xffffffffu, mx, o, 8));
    float sm = 0.f;
    for (int i=0;i<64;i++){
        int z = ln + i*8;
        float e = expf(s1[row][z] - mx);
        s1[row][z] = e; sm += e;
    }
#pragma unroll
    for (int o=4;o>0;o>>=1) sm += __shfl_xor_sync(0xffffffffu, sm, o, 8);
    float inv = 1.f/sm;
    for (int i=0;i<64;i++){
        int z = ln + i*8;
        float v2 = bilc[(long)(l*3+0)*512+z] + bilc[(long)(l*3+1)*512+z] + bilc[(long)(l*3+2)*512+z];
#pragma unroll
        for (int a=0;a<3;a++)
            v2 += tp[((long)((2*l+1)*3+a))*BH + (long)b*512 + z];
        s1[row][z] = s1[row][z] * inv * sigf(v2);
    }
    __syncthreads();

    const int tx = tid&15, ty = tid>>4;
    const int wlm = tid>>1, wlk = (tid&1)<<3;
    float acc[2][4];
#pragma unroll
    for (int i=0;i<2;i++)
#pragma unroll
        for (int j=0;j<4;j++) acc[i][j]=0.f;
    for (int k0=0;k0<512;k0+=16){
        const float* wp = Wsl + (long)(n0+wlm)*2560 + l*512 + k0+wlk;
        float4 u0, u1;
        asm("ld.global.L2::cache_hint.v4.f32 {%0,%1,%2,%3}, [%4], %5;"
            : "=f"(u0.x),"=f"(u0.y),"=f"(u0.z),"=f"(u0.w) : "l"(wp), "l"(PL));
        asm("ld.global.L2::cache_hint.v4.f32 {%0,%1,%2,%3}, [%4], %5;"
            : "=f"(u1.x),"=f"(u1.y),"=f"(u1.z),"=f"(u1.w) : "l"(wp+4), "l"(PL));
        Ws[wlk][wlm]=u0.x; Ws[wlk+1][wlm]=u0.y; Ws[wlk+2][wlm]=u0.z; Ws[wlk+3][wlm]=u0.w;
        Ws[wlk+4][wlm]=u1.x; Ws[wlk+5][wlm]=u1.y; Ws[wlk+6][wlm]=u1.z; Ws[wlk+7][wlm]=u1.w;
        __syncthreads();
#pragma unroll
        for (int kk=0;kk<16;kk++){
            float a0 = s1[ty*2][k0+kk], a1 = s1[ty*2+1][k0+kk];
            float4 w = *(const float4*)&Ws[kk][tx*4];
            acc[0][0]+=a0*w.x; acc[0][1]+=a0*w.y; acc[0][2]+=a0*w.z; acc[0][3]+=a0*w.w;
            acc[1][0]+=a1*w.x; acc[1][1]+=a1*w.y; acc[1][2]+=a1*w.z; acc[1][3]+=a1*w.w;
        }
        __syncthreads();
    }
#pragma unroll
    for (int i=0;i<2;i++)
#pragma unroll
        for (int j=0;j<4;j++)
            part[(long)l*BH + (long)(m0+ty*2+i)*512 + n0+tx*4+j] = acc[i][j];
}

__global__ void y_kernel(const float* __restrict__ part, const float* __restrict__ bsl,
                         __nv_bfloat16* __restrict__ hgh, __nv_bfloat16* __restrict__ hgl,
                         const float* __restrict__ wlin_t,
                         const float* __restrict__ blin_t, float* __restrict__ outp)
{
    int b = blockIdx.x, tid = threadIdx.x;
    float s = 0.f;
    for (int j=tid; j<512; j+=128){
        long idx = (long)b*512 + j;
        float h = bsl[j] + part[idx] + part[BH+idx] + part[2L*BH+idx]
                + part[3L*BH+idx] + part[4L*BH+idx];
        __nv_bfloat16 hh = __float2bfloat16(h);
        hgh[idx] = hh;
        hgl[idx] = __float2bfloat16(h - __bfloat162float(hh));
        s += h * wlin_t[j];
    }
    __shared__ float red[128];
    red[tid]=s; __syncthreads();
    for (int st=64; st>0; st>>=1){ if (tid<st) red[tid]+=red[tid+st]; __syncthreads(); }
    if (tid==0) outp[b] = red[0] + blin_t[0];
}

extern "C" void kernel_launch(void* const* d_in, const int* in_sizes, int n_in,
                              void* d_out, int out_size)
{
    const float* x     = (const float*)d_in[0];
    const float* Wx    = (const float*)d_in[1];
    const float* Wh    = (const float*)d_in[2];
    const float* bl    = (const float*)d_in[3];
    const float* Wg_h  = (const float*)d_in[4];
    const float* Wg_p  = (const float*)d_in[5];
    const float* bg    = (const float*)d_in[6];
    const float* Wilc  = (const float*)d_in[7];
    const float* bilc  = (const float*)d_in[8];
    const float* Wsl   = (const float*)d_in[9];
    const float* bsl   = (const float*)d_in[10];
    const float* Wlin  = (const float*)d_in[11];
    const float* blin  = (const float*)d_in[12];
    float* out = (float*)d_out;

    float *c, *tp, *slp;
    __nv_bfloat16 *wxh, *wxl, *whh, *whl, *xh, *xl, *hbh, *hbl;
    __nv_bfloat16 *ghh, *ghl, *gph, *gpl, *hgh, *hgl;
    __nv_bfloat16 *wth, *wtl, *ichi, *iclo, *cchi, *cclo;
    cudaGetSymbolAddress((void**)&c,   g_c);
    cudaGetSymbolAddress((void**)&tp,  g_tp);
    cudaGetSymbolAddress((void**)&slp, g_slp);
    cudaGetSymbolAddress((void**)&wxh, g_Wxhi);
    cudaGetSymbolAddress((void**)&wxl, g_Wxlo);
    cudaGetSymbolAddress((void**)&whh, g_Whhi);
    cudaGetSymbolAddress((void**)&whl, g_Whlo);
    cudaGetSymbolAddress((void**)&ghh, g_Wghh);
    cudaGetSymbolAddress((void**)&ghl, g_Wghl);
    cudaGetSymbolAddress((void**)&gph, g_Wgph);
    cudaGetSymbolAddress((void**)&gpl, g_Wgpl);
    cudaGetSymbolAddress((void**)&wth, g_Wthi);
    cudaGetSymbolAddress((void**)&wtl, g_Wtlo);
    cudaGetSymbolAddress((void**)&xh,  g_xh);
    cudaGetSymbolAddress((void**)&xl,  g_xl);
    cudaGetSymbolAddress((void**)&hbh, g_hbh);
    cudaGetSymbolAddress((void**)&hbl, g_hbl);
    cudaGetSymbolAddress((void**)&hgh, g_hgh);
    cudaGetSymbolAddress((void**)&hgl, g_hgl);
    cudaGetSymbolAddress((void**)&ichi, g_ichi);
    cudaGetSymbolAddress((void**)&iclo, g_iclo);
    cudaGetSymbolAddress((void**)&cchi, g_cchi);
    cudaGetSymbolAddress((void**)&cclo, g_cclo);

    int devi = 0, nsm = 148, occ = 0;
    cudaGetDevice(&devi);
    cudaDeviceGetAttribute(&nsm, cudaDevAttrMultiProcessorCount, devi);
    cudaOccupancyMaxActiveBlocksPerMultiprocessor(&occ, lstm5_mma, 128, 0);
    bool fused = ((long)occ * nsm >= 384);

    conv_w_lstm<<<1024,256>>>(Wx, Wh, wxh, wxl, whh, whl);
    conv_wg<<<1024,256>>>(Wg_h, Wg_p, ghh, ghl, gph, gpl);
    conv_wilc<<<dim3(16,16,15),256>>>(Wilc, wth, wtl);
    conv_x<<<512,256>>>(x, xh, xl);
    zero_kernel<<<256,256>>>(c, hbh, hbl, hgh, hgl);

    for (int t=0; t<TT; t++){
        int p = t & 1, q = p ^ 1;
        const float* cp = c + (long)p*NLA*BH;
        float*       cq = c + (long)q*NLA*BH;
        const __nv_bfloat16* hbhp = hbh + (long)p*NLA*BH;
        __nv_bfloat16*       hbhq = hbh + (long)q*NLA*BH;
        const __nv_bfloat16* hblp = hbl + (long)p*NLA*BH;
        __nv_bfloat16*       hblq = hbl + (long)q*NLA*BH;
        const __nv_bfloat16* hghp = hgh + (long)p*BH;
        __nv_bfloat16*       hghq = hgh + (long)q*BH;
        const __nv_bfloat16* hglp = hgl + (long)p*BH;
        __nv_bfloat16*       hglq = hgl + (long)q*BH;

        if (fused){
            lstm5_mma<<<dim3(32,4,3),128>>>(
                xh + (long)t*BH, xl + (long)t*BH,
                hbhp, hblp, hbhq, hblq,
                wxh, wxl, whh, whl,
                bl, cp, cq);
        } else {
            for (int l=0; l<5; l++){
                const __nv_bfloat16 *A1h_, *A1l_;
                long a1zs;
                if (l==0){ A1h_ = xh + (long)t*BH; A1l_ = xl + (long)t*BH; a1zs = 0; }
                else { A1h_ = hbhq + (long)(l-1)*3*BH; A1l_ = hblq + (long)(l-1)*3*BH; a1zs = BH; }
                lstm_mma<<<dim3(32,4,3),128>>>(
                    A1h_, A1l_, a1zs,
                    hbhp + (long)l*3*BH, hblp + (long)l*3*BH,
                    wxh + (long)l*4*HH, wxl + (long)l*4*HH,
                    whh + (long)l*4*HH, whl + (long)l*4*HH,
                    bl, l, cp + (long)l*3*BH,
                    cq + (long)l*3*BH,
                    hbhq + (long)l*3*BH, hblq + (long)l*3*BH);
            }
        }
        cell_mma<<<dim3(16,4,15),192>>>(
            hghp, hglp, hbhq, hblq,
            ghh, ghl, gph, gpl,
            bg, cq, ichi, iclo, cchi, cclo);
        t12_mma<<<dim3(16,4,15),128>>>(ichi, iclo, cchi, cclo, wth, wtl, tp);
        combsl<<<dim3(8,8,5),128>>>(tp, bilc, Wsl, slp);
        y_kernel<<<128,128>>>(slp, bsl, hghq, hglq, Wlin + (long)t*HD, blin + t, out + (long)t*BSZ);
    }
}

// round 14
// speedup vs baseline: 1.0062x; 1.0062x over previous
#include <cuda_runtime.h>
#include <cuda_bf16.h>
#include <math.h>
#include <stdint.h>

#define TT 64
#define BSZ 128
#define HD 512
#define NLA 15
#define BH (BSZ*HD)
#define HH (HD*HD)
#define NWL (3L*5*4*512*512)
#define NWG (5L*3*3*512*512)

__device__ float g_c[2][NLA][BH];
__device__ float g_tp[30][BH];
__device__ float g_slp[5][BH];
__device__ volatile unsigned g_bar;
__device__ volatile unsigned g_bar2;

__device__ __nv_bfloat16 g_Wxhi[NWL], g_Wxlo[NWL], g_Whhi[NWL], g_Whlo[NWL];
__device__ __nv_bfloat16 g_Wghh[NWG], g_Wghl[NWG], g_Wgph[NWG], g_Wgpl[NWG];
__device__ __nv_bfloat16 g_Wthi[15L*HH], g_Wtlo[15L*HH];
__device__ __nv_bfloat16 g_xh[(long)TT*BH], g_xl[(long)TT*BH];
__device__ __nv_bfloat16 g_hbh[2][NLA][BH], g_hbl[2][NLA][BH];
__device__ __nv_bfloat16 g_hgh[2][BH], g_hgl[2][BH];
__device__ __nv_bfloat16 g_ichi[NLA][BH], g_iclo[NLA][BH];
__device__ __nv_bfloat16 g_cchi[NLA][BH], g_cclo[NLA][BH];

__device__ __forceinline__ float sigf(float x){ return 1.0f/(1.0f+expf(-x)); }

__global__ void conv_w_lstm(const float* __restrict__ Wx, const float* __restrict__ Wh,
    __nv_bfloat16* xh, __nv_bfloat16* xl, __nv_bfloat16* hh, __nv_bfloat16* hl){
    for (long i = (long)blockIdx.x*blockDim.x+threadIdx.x; i < NWL;
         i += (long)gridDim.x*blockDim.x){
        float w = Wx[i];
        __nv_bfloat16 hi = __float2bfloat16(w);
        xh[i] = hi; xl[i] = __float2bfloat16(w - __bfloat162float(hi));
        w = Wh[i];
        hi = __float2bfloat16(w);
        hh[i] = hi; hl[i] = __float2bfloat16(w - __bfloat162float(hi));
    }
}

// merged: conv_wg + conv_x + zero-state
__global__ void init_misc(const float* __restrict__ Gh, const float* __restrict__ Gp,
    __nv_bfloat16* ghh, __nv_bfloat16* ghl, __nv_bfloat16* gph, __nv_bfloat16* gpl,
    const float* __restrict__ x, __nv_bfloat16* xh, __nv_bfloat16* xl,
    float* c0, __nv_bfloat16* hbh0, __nv_bfloat16* hbl0,
    __nv_bfloat16* hgh0, __nv_bfloat16* hgl0){
    const long NX = (long)TT*BH;
    const long NZ = (long)NLA*BH;
    __nv_bfloat16 z = __float2bfloat16(0.f);
    for (long i = (long)blockIdx.x*blockDim.x+threadIdx.x; i < NWG;
         i += (long)gridDim.x*blockDim.x){
        float w = Gh[i];
        __nv_bfloat16 hi = __float2bfloat16(w);
        ghh[i] = hi; ghl[i] = __float2bfloat16(w - __bfloat162float(hi));
        w = Gp[i];
        hi = __float2bfloat16(w);
        gph[i] = hi; gpl[i] = __float2bfloat16(w - __bfloat162float(hi));
        if (i < NX){
            w = x[i];
            hi = __float2bfloat16(w);
            xh[i] = hi; xl[i] = __float2bfloat16(w - __bfloat162float(hi));
        }
        if (i < NZ){
            c0[i] = 0.f; hbh0[i] = z; hbl0[i] = z;
            if (i < BH){ hgh0[i] = z; hgl0[i] = z; }
        }
    }
}

__global__ void conv_wilc(const float* __restrict__ W,
                          __nv_bfloat16* th, __nv_bfloat16* tl){
    int zb = blockIdx.z;
    int z0 = blockIdx.y*32, y0 = blockIdx.x*32;
    __shared__ float s[32][33];
    int tx = threadIdx.x&31, ty = threadIdx.x>>5;
    const float* Wb = W + (long)zb*HH;
#pragma unroll
    for (int r=0;r<4;r++)
        s[ty+r*8][tx] = Wb[(long)(z0+ty+r*8)*512 + y0+tx];
    __syncthreads();
#pragma unroll
    for (int r=0;r<4;r++){
        float w = s[tx][ty+r*8];
        __nv_bfloat16 hi = __float2bfloat16(w);
        long o = (long)zb*HH + (long)(y0+ty+r*8)*512 + z0+tx;
        th[o]=hi; tl[o]=__float2bfloat16(w - __bfloat162float(hi));
    }
}

__device__ __forceinline__ void ldsm4(uint32_t addr, uint32_t &r0, uint32_t &r1,
                                      uint32_t &r2, uint32_t &r3){
    asm volatile("ldmatrix.sync.aligned.m8n8.x4.shared.b16 {%0,%1,%2,%3}, [%4];"
        : "=r"(r0),"=r"(r1),"=r"(r2),"=r"(r3) : "r"(addr));
}
__device__ __forceinline__ void mma16816(float* c, const uint32_t* a,
                                         uint32_t b0, uint32_t b1){
    asm volatile("mma.sync.aligned.m16n8k16.row.col.f32.bf16.bf16.f32 "
        "{%0,%1,%2,%3},{%4,%5,%6,%7},{%8,%9},{%0,%1,%2,%3};"
        : "+f"(c[0]),"+f"(c[1]),"+f"(c[2]),"+f"(c[3])
        : "r"(a[0]),"r"(a[1]),"r"(a[2]),"r"(a[3]),"r"(b0),"r"(b1));
}
__device__ __forceinline__ void cpa16(uint32_t dst, const void* src){
    asm volatile("cp.async.ca.shared.global [%0], [%1], 16;" :: "r"(dst), "l"(src));
}
__device__ __forceinline__ void cpa_commit(){ asm volatile("cp.async.commit_group;"); }

__device__ __forceinline__ void grid_barrier(volatile unsigned* bar, unsigned nblocks){
    __syncthreads();
    __threadfence();
    if (threadIdx.x == 0){
        unsigned token = atomicAdd((unsigned*)bar, 1u);
        unsigned target = (token/nblocks + 1u)*nblocks;
        while (*bar < target) { }
    }
    __syncthreads();
}

// ---- fused 5-level LSTM: persistent, grid barrier between levels -------------
__global__ __launch_bounds__(128,3) void lstm5_mma(
    const __nv_bfloat16* __restrict__ xh_t, const __nv_bfloat16* __restrict__ xl_t,
    const __nv_bfloat16* __restrict__ hbhp, const __nv_bfloat16* __restrict__ hblp,
    __nv_bfloat16* __restrict__ hbhq, __nv_bfloat16* __restrict__ hblq,
    const __nv_bfloat16* __restrict__ wxh, const __nv_bfloat16* __restrict__ wxl,
    const __nv_bfloat16* __restrict__ whh, const __nv_bfloat16* __restrict__ whl,
    const float* __restrict__ bl, const float* __restrict__ cpb,
    float* __restrict__ cqb)
{
    const int a = blockIdx.z;
    const int m0 = blockIdx.y*32, n0 = blockIdx.x*16;
    const int tid = threadIdx.x, lane = tid&31, g = tid>>5;

    __shared__ __align__(16) __nv_bfloat16 sA[3][2][32][40];
    __shared__ __align__(16) __nv_bfloat16 sW[3][2][4][16][40];

    const uint32_t sA_base = (uint32_t)__cvta_generic_to_shared(&sA[0][0][0][0]);
    const uint32_t sW_base = (uint32_t)__cvta_generic_to_shared(&sW[0][0][0][0][0]);

    const int a_row = lane&15, a_ko = (lane>>4)*8;
    const int b_r = lane&7, b_sel = lane>>3;
    const int b_rowoff = b_r + ((b_sel>>1)?8:0), b_ko = (b_sel&1)*8;

    for (int l=0; l<5; l++){
        const __nv_bfloat16* Ah_[2];
        const __nv_bfloat16* Al_[2];
        if (l==0){ Ah_[0] = xh_t; Al_[0] = xl_t; }
        else { Ah_[0] = hbhq + (long)((l-1)*3+a)*BH; Al_[0] = hblq + (long)((l-1)*3+a)*BH; }
        Ah_[1] = hbhp + (long)(l*3+a)*BH;
        Al_[1] = hblp + (long)(l*3+a)*BH;
        const __nv_bfloat16* Wp[2][2] = {
            {wxh + (long)(a*20+l*4)*HH, wxl + (long)(a*20+l*4)*HH},
            {whh + (long)(a*20+l*4)*HH, whl + (long)(a*20+l*4)*HH}};

        float C[2][2][4];
#pragma unroll
        for (int mh=0;mh<2;mh++)
#pragma unroll
            for (int f=0;f<2;f++)
#pragma unroll
                for (int r=0;r<4;r++) C[mh][f][r]=0.f;

        auto prefetch = [&](int kc2){
            int st = kc2 % 3, s = kc2>>4, k0 = (kc2&15)*32;
#pragma unroll
            for (int it=0; it<2; it++){
                int idx = tid + it*128;
                int q = idx&3, row = (idx>>2)&31, hl = (idx>>7)&1;
                const __nv_bfloat16* src = (hl ? Al_[s] : Ah_[s]) + (long)(m0+row)*512 + k0 + q*8;
                cpa16(sA_base + (uint32_t)((((st*2+hl)*32 + row)*40 + q*8)*2), src);
            }
#pragma unroll
            for (int it=0; it<4; it++){
                int idx = tid + it*128;
                int q = idx&3, n = (idx>>2)&15, gg = (idx>>6)&3, hl = (idx>>8)&1;
                const __nv_bfloat16* src = Wp[s][hl] + (long)gg*HH + (long)(n0+n)*512 + k0 + q*8;
                cpa16(sW_base + (uint32_t)(((((st*2+hl)*4+gg)*16 + n)*40 + q*8)*2), src);
            }
            cpa_commit();
        };

        prefetch(0); prefetch(1);
        for (int kc2=0; kc2<32; kc2++){
            const int st = kc2 % 3;
            if (kc2+2 < 32){
                prefetch(kc2+2);
                asm volatile("cp.async.wait_group 2;");
            } else if (kc2+1 < 32){
                asm volatile("cp.async.wait_group 1;");
            } else {
                asm volatile("cp.async.wait_group 0;");
            }
            __syncthreads();
#pragma unroll
            for (int kf=0;kf<2;kf++){
                uint32_t ah[2][4], al[2][4];
#pragma unroll
                for (int mh=0;mh<2;mh++){
                    uint32_t ad = sA_base + (uint32_t)(((((st*2+0)*32) + mh*16 + a_row)*40 + kf*16 + a_ko)*2);
                    ldsm4(ad, ah[mh][0], ah[mh][1], ah[mh][2], ah[mh][3]);
                    ad = sA_base + (uint32_t)(((((st*2+1)*32) + mh*16 + a_row)*40 + kf*16 + a_ko)*2);
                    ldsm4(ad, al[mh][0], al[mh][1], al[mh][2], al[mh][3]);
                }
                uint32_t bh0,bh1,bh2,bh3, bl0,bl1,bl2,bl3;
                {
                    uint32_t bd = sW_base + (uint32_t)(((((st*2+0)*4+g)*16 + b_rowoff)*40 + kf*16 + b_ko)*2);
                    ldsm4(bd, bh0,bh1,bh2,bh3);
                    bd = sW_base + (uint32_t)(((((st*2+1)*4+g)*16 + b_rowoff)*40 + kf*16 + b_ko)*2);
                    ldsm4(bd, bl0,bl1,bl2,bl3);
                }
#pragma unroll
                for (int mh=0;mh<2;mh++){
                    mma16816(C[mh][0], ah[mh], bh0, bh1);
                    mma16816(C[mh][1], ah[mh], bh2, bh3);
                    mma16816(C[mh][0], ah[mh], bl0, bl1);
                    mma16816(C[mh][1], ah[mh], bl2, bl3);
                    mma16816(C[mh][0], al[mh], bh0, bh1);
                    mma16816(C[mh][1], al[mh], bh2, bh3);
                }
            }
            __syncthreads();
        }

        float* preS = (float*)&sW[0][0][0][0][0];
        {
            int r = lane>>2, i2 = (lane&3)*2;
#pragma unroll
            for (int mh=0;mh<2;mh++)
#pragma unroll
                for (int f=0;f<2;f++){
                    int col = f*8 + i2;
                    preS[(g*32 + mh*16 + r)*16 + col]     = C[mh][f][0];
                    preS[(g*32 + mh*16 + r)*16 + col+1]   = C[mh][f][1];
                    preS[(g*32 + mh*16 + r+8)*16 + col]   = C[mh][f][2];
                    preS[(g*32 + mh*16 + r+8)*16 + col+1] = C[mh][f][3];
                }
        }
        __syncthreads();
        {
            const float* cp = cpb + (long)(l*3+a)*BH;
            float* cq = cqb + (long)(l*3+a)*BH;
            __nv_bfloat16* hh_out = hbhq + (long)(l*3+a)*BH;
            __nv_bfloat16* hl_out = hblq + (long)(l*3+a)*BH;
            for (int cell = tid; cell < 512; cell += 128){
                int m = cell>>4, n = cell&15;
                int gn = n0 + n;
                float p[4];
#pragma unroll
                for (int gg=0;gg<4;gg++)
                    p[gg] = preS[(gg*32+m)*16 + n] + bl[((long)(a*5+l)*4+gg)*512 + gn];
                long o = (long)(m0+m)*512 + gn;
                float cn = sigf(p[1])*cp[o] + sigf(p[0])*tanhf(p[2]);
                float hv = sigf(p[3])*tanhf(cn);
                cq[o] = cn;
                __nv_bfloat16 hh = __float2bfloat16(hv);
                hh_out[o] = hh;
                hl_out[o] = __float2bfloat16(hv - __bfloat162float(hh));
            }
        }
        if (l < 4) grid_barrier(&g_bar, 384u);
    }
}

// ---- single-level LSTM fallback ----------------------------------------------
__global__ __launch_bounds__(128) void lstm_mma(
    const __nv_bfloat16* __restrict__ A1h, const __nv_bfloat16* __restrict__ A1l, long a1zs,
    const __nv_bfloat16* __restrict__ A2h, const __nv_bfloat16* __restrict__ A2l,
    const __nv_bfloat16* __restrict__ W1h, const __nv_bfloat16* __restrict__ W1l,
    const __nv_bfloat16* __restrict__ W2h, const __nv_bfloat16* __restrict__ W2l,
    const float* __restrict__ bl, int l, const float* __restrict__ cpb,
    float* __restrict__ cqb,
    __nv_bfloat16* __restrict__ hbhq, __nv_bfloat16* __restrict__ hblq)
{
    const int a = blockIdx.z;
    const int m0 = blockIdx.y*32, n0 = blockIdx.x*16;
    const int tid = threadIdx.x, lane = tid&31, g = tid>>5;

    __shared__ __align__(16) __nv_bfloat16 sA[3][2][32][40];
    __shared__ __align__(16) __nv_bfloat16 sW[3][2][4][16][40];

    float C[2][2][4];
#pragma unroll
    for (int mh=0;mh<2;mh++)
#pragma unroll
        for (int f=0;f<2;f++)
#pragma unroll
            for (int r=0;r<4;r++) C[mh][f][r]=0.f;

    const __nv_bfloat16* Ah_[2] = {A1h + (long)a*a1zs, A2h + (long)a*BH};
    const __nv_bfloat16* Al_[2] = {A1l + (long)a*a1zs, A2l + (long)a*BH};
    const __nv_bfloat16* Wp[2][2] = {
        {W1h + (long)a*20*HH, W1l + (long)a*20*HH},
        {W2h + (long)a*20*HH, W2l + (long)a*20*HH}};

    const uint32_t sA_base = (uint32_t)__cvta_generic_to_shared(&sA[0][0][0][0]);
    const uint32_t sW_base = (uint32_t)__cvta_generic_to_shared(&sW[0][0][0][0][0]);

    const int a_row = lane&15, a_ko = (lane>>4)*8;
    const int b_r = lane&7, b_sel = lane>>3;
    const int b_rowoff = b_r + ((b_sel>>1)?8:0), b_ko = (b_sel&1)*8;

    auto prefetch = [&](int kc2){
        int st = kc2 % 3, s = kc2>>4, k0 = (kc2&15)*32;
#pragma unroll
        for (int it=0; it<2; it++){
            int idx = tid + it*128;
            int q = idx&3, row = (idx>>2)&31, hl = (idx>>7)&1;
            const __nv_bfloat16* src = (hl ? Al_[s] : Ah_[s]) + (long)(m0+row)*512 + k0 + q*8;
            cpa16(sA_base + (uint32_t)((((st*2+hl)*32 + row)*40 + q*8)*2), src);
        }
#pragma unroll
        for (int it=0; it<4; it++){
            int idx = tid + it*128;
            int q = idx&3, n = (idx>>2)&15, gg = (idx>>6)&3, hl = (idx>>8)&1;
            const __nv_bfloat16* src = Wp[s][hl] + (long)gg*HH + (long)(n0+n)*512 + k0 + q*8;
            cpa16(sW_base + (uint32_t)(((((st*2+hl)*4+gg)*16 + n)*40 + q*8)*2), src);
        }
        cpa_commit();
    };

    prefetch(0); prefetch(1);
    for (int kc2=0; kc2<32; kc2++){
        const int st = kc2 % 3;
        if (kc2+2 < 32){
            prefetch(kc2+2);
            asm volatile("cp.async.wait_group 2;");
        } else if (kc2+1 < 32){
            asm volatile("cp.async.wait_group 1;");
        } else {
            asm volatile("cp.async.wait_group 0;");
        }
        __syncthreads();
#pragma unroll
        for (int kf=0;kf<2;kf++){
            uint32_t ah[2][4], al[2][4];
#pragma unroll
            for (int mh=0;mh<2;mh++){
                uint32_t ad = sA_base + (uint32_t)(((((st*2+0)*32) + mh*16 + a_row)*40 + kf*16 + a_ko)*2);
                ldsm4(ad, ah[mh][0], ah[mh][1], ah[mh][2], ah[mh][3]);
                ad = sA_base + (uint32_t)(((((st*2+1)*32) + mh*16 + a_row)*40 + kf*16 + a_ko)*2);
                ldsm4(ad, al[mh][0], al[mh][1], al[mh][2], al[mh][3]);
            }
            uint32_t bh0,bh1,bh2,bh3, bl0,bl1,bl2,bl3;
            {
                uint32_t bd = sW_base + (uint32_t)(((((st*2+0)*4+g)*16 + b_rowoff)*40 + kf*16 + b_ko)*2);
                ldsm4(bd, bh0,bh1,bh2,bh3);
                bd = sW_base + (uint32_t)(((((st*2+1)*4+g)*16 + b_rowoff)*40 + kf*16 + b_ko)*2);
                ldsm4(bd, bl0,bl1,bl2,bl3);
            }
#pragma unroll
            for (int mh=0;mh<2;mh++){
                mma16816(C[mh][0], ah[mh], bh0, bh1);
                mma16816(C[mh][1], ah[mh], bh2, bh3);
                mma16816(C[mh][0], ah[mh], bl0, bl1);
                mma16816(C[mh][1], ah[mh], bl2, bl3);
                mma16816(C[mh][0], al[mh], bh0, bh1);
                mma16816(C[mh][1], al[mh], bh2, bh3);
            }
        }
        __syncthreads();
    }

    float* preS = (float*)&sW[0][0][0][0][0];
    {
        int r = lane>>2, i2 = (lane&3)*2;
#pragma unroll
        for (int mh=0;mh<2;mh++)
#pragma unroll
            for (int f=0;f<2;f++){
                int col = f*8 + i2;
                preS[(g*32 + mh*16 + r)*16 + col]     = C[mh][f][0];
                preS[(g*32 + mh*16 + r)*16 + col+1]   = C[mh][f][1];
                preS[(g*32 + mh*16 + r+8)*16 + col]   = C[mh][f][2];
                preS[(g*32 + mh*16 + r+8)*16 + col+1] = C[mh][f][3];
            }
    }
    __syncthreads();
    {
        const float* cp = cpb + (long)a*BH;
        for (int cell = tid; cell < 512; cell += 128){
            int m = cell>>4, n = cell&15;
            int gn = n0 + n;
            float p[4];
#pragma unroll
            for (int gg=0;gg<4;gg++)
                p[gg] = preS[(gg*32+m)*16 + n] + bl[((long)(a*5+l)*4+gg)*512 + gn];
            long o = (long)a*BH + (long)(m0+m)*512 + gn;
            float cn = sigf(p[1])*cp[(long)(m0+m)*512+gn] + sigf(p[0])*tanhf(p[2]);
            float hv = sigf(p[3])*tanhf(cn);
            cqb[o] = cn;
            __nv_bfloat16 hh = __float2bfloat16(hv);
            hbhq[o] = hh;
            hblq[o] = __float2bfloat16(hv - __bfloat162float(hh));
        }
    }
}

// ---- cell block: 2-stage split-bf16 3-gate mma -------------------------------
__global__ __launch_bounds__(192) void cell_mma(
    const __nv_bfloat16* __restrict__ Hgh, const __nv_bfloat16* __restrict__ Hgl,
    const __nv_bfloat16* __restrict__ Hbh, const __nv_bfloat16* __restrict__ Hbl,
    const __nv_bfloat16* __restrict__ Ghh, const __nv_bfloat16* __restrict__ Ghl,
    const __nv_bfloat16* __restrict__ Gph, const __nv_bfloat16* __restrict__ Gpl,
    const float* __restrict__ bg, const float* __restrict__ scb,
    __nv_bfloat16* __restrict__ ichi, __nv_bfloat16* __restrict__ iclo,
    __nv_bfloat16* __restrict__ cchi, __nv_bfloat16* __restrict__ cclo)
{
    const int zb = blockIdx.z;
    const int m0 = blockIdx.y*32, n0 = blockIdx.x*32;
    const int tid = threadIdx.x, lane = tid&31, wid = tid>>5;
    const int g = wid>>1, nb = (wid&1)*16;

    __shared__ __align__(16) __nv_bfloat16 sA[2][2][32][40];
    __shared__ __align__(16) __nv_bfloat16 sW[2][2][3][32][40];

    float C[2][2][4];
#pragma unroll
    for (int mh=0;mh<2;mh++)
#pragma unroll
        for (int f=0;f<2;f++)
#pragma unroll
            for (int r=0;r<4;r++) C[mh][f][r]=0.f;

    const __nv_bfloat16* Ah_[2] = {Hgh, Hbh + (long)zb*BH};
    const __nv_bfloat16* Al_[2] = {Hgl, Hbl + (long)zb*BH};
    const __nv_bfloat16* Wp[2][2] = {
        {Ghh + (long)zb*3*HH, Ghl + (long)zb*3*HH},
        {Gph + (long)zb*3*HH, Gpl + (long)zb*3*HH}};

    const uint32_t sA_base = (uint32_t)__cvta_generic_to_shared(&sA[0][0][0][0]);
    const uint32_t sW_base = (uint32_t)__cvta_generic_to_shared(&sW[0][0][0][0][0]);

    const int a_row = lane&15, a_ko = (lane>>4)*8;
    const int b_r = lane&7, b_sel = lane>>3;
    const int b_rowoff = b_r + ((b_sel>>1)?8:0), b_ko = (b_sel&1)*8;

    auto prefetch = [&](int kc2){
        int st = kc2&1, s = kc2>>4, k0 = (kc2&15)*32;
#pragma unroll
        for (int it=0; it<2; it++){
            int idx = tid + it*192;
            if (idx < 256){
                int hl = idx>>7, lm = (idx>>2)&31, lq = idx&3;
                const __nv_bfloat16* src = (hl ? Al_[s] : Ah_[s]) + (long)(m0+lm)*512 + k0 + lq*8;
                cpa16(sA_base + (uint32_t)((((st*2+hl)*32 + lm)*40 + lq*8)*2), src);
            }
        }
#pragma unroll
        for (int it=0; it<4; it++){
            int idx = tid + it*192;
            int q = idx&3, n = (idx>>2)&31, rest = idx>>7;
            int gg = rest % 3, hl = rest / 3;
            const __nv_bfloat16* src = Wp[s][hl] + (long)gg*HH + (long)(n0+n)*512 + k0 + q*8;
            cpa16(sW_base + (uint32_t)(((((st*2+hl)*3+gg)*32 + n)*40 + q*8)*2), src);
        }
        cpa_commit();
    };

    prefetch(0);
    for (int kc2=0; kc2<32; kc2++){
        const int st = kc2&1;
        if (kc2+1 < 32){
            prefetch(kc2+1);
            asm volatile("cp.async.wait_group 1;");
        } else {
            asm volatile("cp.async.wait_group 0;");
        }
        __syncthreads();
#pragma unroll
        for (int kf=0;kf<2;kf++){
            uint32_t ah[2][4], al[2][4];
#pragma unroll
            for (int mh=0;mh<2;mh++){
                uint32_t ad = sA_base + (uint32_t)(((((st*2+0)*32) + mh*16 + a_row)*40 + kf*16 + a_ko)*2);
                ldsm4(ad, ah[mh][0], ah[mh][1], ah[mh][2], ah[mh][3]);
                ad = sA_base + (uint32_t)(((((st*2+1)*32) + mh*16 + a_row)*40 + kf*16 + a_ko)*2);
                ldsm4(ad, al[mh][0], al[mh][1], al[mh][2], al[mh][3]);
            }
            uint32_t bh0,bh1,bh2,bh3, bl0,bl1,bl2,bl3;
            {
                uint32_t bd = sW_base + (uint32_t)((((((st*2+0)*3)+g)*32 + nb + b_rowoff)*40 + kf*16 + b_ko)*2);
                ldsm4(bd, bh0,bh1,bh2,bh3);
                bd = sW_base + (uint32_t)((((((st*2+1)*3)+g)*32 + nb + b_rowoff)*40 + kf*16 + b_ko)*2);
                ldsm4(bd, bl0,bl1,bl2,bl3);
            }
#pragma unroll
            for (int mh=0;mh<2;mh++){
                mma16816(C[mh][0], ah[mh], bh0, bh1);
                mma16816(C[mh][1], ah[mh], bh2, bh3);
                mma16816(C[mh][0], ah[mh], bl0, bl1);
                mma16816(C[mh][1], ah[mh], bl2, bl3);
                mma16816(C[mh][0], al[mh], bh0, bh1);
                mma16816(C[mh][1], al[mh], bh2, bh3);
            }
        }
        __syncthreads();
    }

    float* preS = (float*)&sW[0][0][0][0][0];
    {
        int r = lane>>2, i2 = (lane&3)*2;
#pragma unroll
        for (int mh=0;mh<2;mh++)
#pragma unroll
            for (int f=0;f<2;f++){
                int col = nb + f*8 + i2;
                preS[(g*32 + mh*16 + r)*32 + col]     = C[mh][f][0];
                preS[(g*32 + mh*16 + r)*32 + col+1]   = C[mh][f][1];
                preS[(g*32 + mh*16 + r+8)*32 + col]   = C[mh][f][2];
                preS[(g*32 + mh*16 + r+8)*32 + col+1] = C[mh][f][3];
            }
    }
    __syncthreads();
    {
        const float* sc = scb + (long)zb*BH;
        for (int cell = tid; cell < 1024; cell += 192){
            int m = cell>>5, n = cell&31;
            int gn = n0 + n;
            float p[3];
#pragma unroll
            for (int gg=0;gg<3;gg++)
                p[gg] = preS[(gg*32+m)*32 + n] + bg[((long)zb*3+gg)*512 + gn];
            long r = (long)(m0+m)*512 + gn;
            float icv = sigf(p[0]) * sc[r];
            float ccv = sigf(p[1])*tanhf(p[2]) + icv;
            long o = (long)zb*BH + r;
            __nv_bfloat16 ih = __float2bfloat16(icv);
            ichi[o] = ih; iclo[o] = __float2bfloat16(icv - __bfloat162float(ih));
            __nv_bfloat16 ch = __float2bfloat16(ccv);
            cchi[o] = ch; cclo[o] = __float2bfloat16(ccv - __bfloat162float(ch));
        }
    }
}

// ---- t12: 2-stage dual-stream split-bf16 mma ---------------------------------
__global__ __launch_bounds__(128) void t12_mma(
    const __nv_bfloat16* __restrict__ ichi, const __nv_bfloat16* __restrict__ iclo,
    const __nv_bfloat16* __restrict__ cchi, const __nv_bfloat16* __restrict__ cclo,
    const __nv_bfloat16* __restrict__ Wth, const __nv_bfloat16* __restrict__ Wtl,
    float* __restrict__ tp)
{
    const int zb = blockIdx.z;
    const int l = zb/3, a = zb%3;
    const int m0 = blockIdx.y*32, n0 = blockIdx.x*32;
    const int tid = threadIdx.x, lane = tid&31, wid = tid>>5;
    const int s = wid>>1, nb = (wid&1)*16;

    __shared__ __align__(16) __nv_bfloat16 sA[2][2][2][32][40];
    __shared__ __align__(16) __nv_bfloat16 sW[2][2][32][40];

    float C[2][2][4];
#pragma unroll
    for (int mh=0;mh<2;mh++)
#pragma unroll
        for (int f=0;f<2;f++)
#pragma unroll
            for (int r=0;r<4;r++) C[mh][f][r]=0.f;

    const __nv_bfloat16* Asrc[2][2] = {
        {ichi + (long)zb*BH, iclo + (long)zb*BH},
        {cchi + (long)zb*BH, cclo + (long)zb*BH}};
    const __nv_bfloat16* Wsrc[2] = {Wth + (long)zb*HH, Wtl + (long)zb*HH};

    const uint32_t sA_base = (uint32_t)__cvta_generic_to_shared(&sA[0][0][0][0][0]);
    const uint32_t sW_base = (uint32_t)__cvta_generic_to_shared(&sW[0][0][0][0]);

    const int a_row = lane&15, a_ko = (lane>>4)*8;
    const int b_r = lane&7, b_sel = lane>>3;
    const int b_rowoff = b_r + ((b_sel>>1)?8:0), b_ko = (b_sel&1)*8;

    auto prefetch = [&](int kc){
        int st = kc&1, k0 = kc*32;
#pragma unroll
        for (int it=0; it<4; it++){
            int idx = tid + it*128;
            int q = idx&3, row = (idx>>2)&31, hl = (idx>>7)&1, ss = (idx>>8)&1;
            const __nv_bfloat16* src = Asrc[ss][hl] + (long)(m0+row)*512 + k0 + q*8;
            cpa16(sA_base + (uint32_t)(((((st*2+ss)*2+hl)*32 + row)*40 + q*8)*2), src);
        }
#pragma unroll
        for (int it=0; it<2; it++){
            int idx = tid + it*128;
            int q = idx&3, row = (idx>>2)&31, hl = (idx>>7)&1;
            const __nv_bfloat16* src = Wsrc[hl] + (long)(n0+row)*512 + k0 + q*8;
            cpa16(sW_base + (uint32_t)((((st*2+hl)*32 + row)*40 + q*8)*2), src);
        }
        cpa_commit();
    };

    prefetch(0);
    for (int kc=0; kc<16; kc++){
        const int st = kc&1;
        if (kc+1 < 16){
            prefetch(kc+1);
            asm volatile("cp.async.wait_group 1;");
        } else {
            asm volatile("cp.async.wait_group 0;");
        }
        __syncthreads();
#pragma unroll
        for (int kf=0;kf<2;kf++){
            uint32_t ah[2][4], al[2][4];
#pragma unroll
            for (int mh=0;mh<2;mh++){
                uint32_t ad = sA_base + (uint32_t)((((((st*2+s)*2+0)*32) + mh*16 + a_row)*40 + kf*16 + a_ko)*2);
                ldsm4(ad, ah[mh][0], ah[mh][1], ah[mh][2], ah[mh][3]);
                ad = sA_base + (uint32_t)((((((st*2+s)*2+1)*32) + mh*16 + a_row)*40 + kf*16 + a_ko)*2);
                ldsm4(ad, al[mh][0], al[mh][1], al[mh][2], al[mh][3]);
            }
            uint32_t bh0,bh1,bh2,bh3, bl0,bl1,bl2,bl3;
            {
                uint32_t bd = sW_base + (uint32_t)((((st*2+0)*32 + nb + b_rowoff)*40 + kf*16 + b_ko)*2);
                ldsm4(bd, bh0,bh1,bh2,bh3);
                bd = sW_base + (uint32_t)((((st*2+1)*32 + nb + b_rowoff)*40 + kf*16 + b_ko)*2);
                ldsm4(bd, bl0,bl1,bl2,bl3);
            }
#pragma unroll
            for (int mh=0;mh<2;mh++){
                mma16816(C[mh][0], ah[mh], bh0, bh1);
                mma16816(C[mh][1], ah[mh], bh2, bh3);
                mma16816(C[mh][0], ah[mh], bl0, bl1);
                mma16816(C[mh][1], ah[mh], bl2, bl3);
                mma16816(C[mh][0], al[mh], bh0, bh1);
                mma16816(C[mh][1], al[mh], bh2, bh3);
            }
        }
        __syncthreads();
    }

    float* tpo = tp + ((long)((2*l+s)*3+a))*BH;
    {
        int r = lane>>2, i2 = (lane&3)*2;
#pragma unroll
        for (int mh=0;mh<2;mh++)
#pragma unroll
            for (int f=0;f<2;f++){
                int row = m0 + mh*16 + r;
                int col = n0 + nb + f*8 + i2;
                tpo[(long)row*512 + col]       = C[mh][f][0];
                tpo[(long)row*512 + col+1]     = C[mh][f][1];
                tpo[(long)(row+8)*512 + col]   = C[mh][f][2];
                tpo[(long)(row+8)*512 + col+1] = C[mh][f][3];
            }
    }
}

// ---- comb + single_li + (persistent) y ---------------------------------------
// TAIL=1: after grid barrier, first 128 blocks compute y and h_g splits.
template <int TAIL>
__global__ __launch_bounds__(128) void combsl(
    const float* __restrict__ tp, const float* __restrict__ bilc,
    const float* __restrict__ Wsl, float* __restrict__ part,
    const float* __restrict__ bsl,
    __nv_bfloat16* __restrict__ hgh, __nv_bfloat16* __restrict__ hgl,
    const float* __restrict__ wlin_t, const float* __restrict__ blin_t,
    float* __restrict__ outp)
{
    const int l = blockIdx.z, m0 = blockIdx.y*16, n0 = blockIdx.x*64;
    __shared__ __align__(16) float s1[16][520];
    __shared__ __align__(16) float Ws[16][68];
    const int tid = threadIdx.x;
    const int row = tid>>3, ln = tid&7;
    const int b = m0 + row;

    float mx = -1e30f;
    for (int i=0;i<64;i++){
        int z = ln + i*8;
        float v1 = bilc[(long)(l*3+0)*512+z] + bilc[(long)(l*3+1)*512+z] + bilc[(long)(l*3+2)*512+z];
#pragma unroll
        for (int a=0;a<3;a++)
            v1 += tp[((long)((2*l+0)*3+a))*BH + (long)b*512 + z];
        s1[row][z] = v1;
        mx = fmaxf(mx, v1);
    }
#pragma unroll
    for (int o=4;o>0;o>>=1) mx = fmaxf(mx, __shfl_xor_sync(0xffffffffu, mx, o, 8));
    float sm = 0.f;
    for (int i=0;i<64;i++){
        int z = ln + i*8;
        float e = expf(s1[row][z] - mx);
        s1[row][z] = e; sm += e;
    }
#pragma unroll
    for (int o=4;o>0;o>>=1) sm += __shfl_xor_sync(0xffffffffu, sm, o, 8);
    float inv = 1.f/sm;
    for (int i=0;i<64;i++){
        int z = ln + i*8;
        float v2 = bilc[(long)(l*3+0)*512+z] + bilc[(long)(l*3+1)*512+z] + bilc[(long)(l*3+2)*512+z];
#pragma unroll
        for (int a=0;a<3;a++)
            v2 += tp[((long)((2*l+1)*3+a))*BH + (long)b*512 + z];
        s1[row][z] = s1[row][z] * inv * sigf(v2);
    }
    __syncthreads();

    const int tx = tid&15, ty = tid>>4;
    const int wlm = tid>>1, wlk = (tid&1)<<3;
    float acc[2][4];
#pragma unroll
    for (int i=0;i<2;i++)
#pragma unroll
        for (int j=0;j<4;j++) acc[i][j]=0.f;
    for (int k0=0;k0<512;k0+=16){
        const float* wp = Wsl + (long)(n0+wlm)*2560 + l*512 + k0+wlk;
        float4 u0=*(const float4*)wp, u1=*(const float4*)(wp+4);
        Ws[wlk][wlm]=u0.x; Ws[wlk+1][wlm]=u0.y; Ws[wlk+2][wlm]=u0.z; Ws[wlk+3][wlm]=u0.w;
        Ws[wlk+4][wlm]=u1.x; Ws[wlk+5][wlm]=u1.y; Ws[wlk+6][wlm]=u1.z; Ws[wlk+7][wlm]=u1.w;
        __syncthreads();
#pragma unroll
        for (int kk=0;kk<16;kk++){
            float a0 = s1[ty*2][k0+kk], a1 = s1[ty*2+1][k0+kk];
            float4 w = *(const float4*)&Ws[kk][tx*4];
            acc[0][0]+=a0*w.x; acc[0][1]+=a0*w.y; acc[0][2]+=a0*w.z; acc[0][3]+=a0*w.w;
            acc[1][0]+=a1*w.x; acc[1][1]+=a1*w.y; acc[1][2]+=a1*w.z; acc[1][3]+=a1*w.w;
        }
        __syncthreads();
    }
#pragma unroll
    for (int i=0;i<2;i++)
#pragma unroll
        for (int j=0;j<4;j++)
            part[(long)l*BH + (long)(m0+ty*2+i)*512 + n0+tx*4+j] = acc[i][j];

    if (TAIL){
        grid_barrier(&g_bar2, 320u);
        int fid = blockIdx.x + (blockIdx.y<<3) + (blockIdx.z<<6);
        if (fid < 128){
            int bb = fid;
            float s = 0.f;
            for (int j=tid; j<512; j+=128){
                long idx = (long)bb*512 + j;
                float h = bsl[j] + part[idx] + part[BH+idx] + part[2L*BH+idx]
                        + part[3L*BH+idx] + part[4L*BH+idx];
                __nv_bfloat16 hh = __float2bfloat16(h);
                hgh[idx] = hh;
                hgl[idx] = __float2bfloat16(h - __bfloat162float(hh));
                s += h * wlin_t[j];
            }
            float* red = &s1[0][0];
            red[tid]=s; __syncthreads();
            for (int st=64; st>0; st>>=1){ if (tid<st) red[tid]+=red[tid+st]; __syncthreads(); }
            if (tid==0) outp[bb] = red[0] + blin_t[0];
        }
    }
}

__global__ void y_kernel(const float* __restrict__ part, const float* __restrict__ bsl,
                         __nv_bfloat16* __restrict__ hgh, __nv_bfloat16* __restrict__ hgl,
                         const float* __restrict__ wlin_t,
                         const float* __restrict__ blin_t, float* __restrict__ outp)
{
    int b = blockIdx.x, tid = threadIdx.x;
    float s = 0.f;
    for (int j=tid; j<512; j+=128){
        long idx = (long)b*512 + j;
        float h = bsl[j] + part[idx] + part[BH+idx] + part[2L*BH+idx]
                + part[3L*BH+idx] + part[4L*BH+idx];
        __nv_bfloat16 hh = __float2bfloat16(h);
        hgh[idx] = hh;
        hgl[idx] = __float2bfloat16(h - __bfloat162float(hh));
        s += h * wlin_t[j];
    }
    __shared__ float red[128];
    red[tid]=s; __syncthreads();
    for (int st=64; st>0; st>>=1){ if (tid<st) red[tid]+=red[tid+st]; __syncthreads(); }
    if (tid==0) outp[b] = red[0] + blin_t[0];
}

extern "C" void kernel_launch(void* const* d_in, const int* in_sizes, int n_in,
                              void* d_out, int out_size)
{
    const float* x     = (const float*)d_in[0];
    const float* Wx    = (const float*)d_in[1];
    const float* Wh    = (const float*)d_in[2];
    const float* bl    = (const float*)d_in[3];
    const float* Wg_h  = (const float*)d_in[4];
    const float* Wg_p  = (const float*)d_in[5];
    const float* bg    = (const float*)d_in[6];
    const float* Wilc  = (const float*)d_in[7];
    const float* bilc  = (const float*)d_in[8];
    const float* Wsl   = (const float*)d_in[9];
    const float* bsl   = (const float*)d_in[10];
    const float* Wlin  = (const float*)d_in[11];
    const float* blin  = (const float*)d_in[12];
    float* out = (float*)d_out;

    float *c, *tp, *slp;
    __nv_bfloat16 *wxh, *wxl, *whh, *whl, *xh, *xl, *hbh, *hbl;
    __nv_bfloat16 *ghh, *ghl, *gph, *gpl, *hgh, *hgl;
    __nv_bfloat16 *wth, *wtl, *ichi, *iclo, *cchi, *cclo;
    cudaGetSymbolAddress((void**)&c,   g_c);
    cudaGetSymbolAddress((void**)&tp,  g_tp);
    cudaGetSymbolAddress((void**)&slp, g_slp);
    cudaGetSymbolAddress((void**)&wxh, g_Wxhi);
    cudaGetSymbolAddress((void**)&wxl, g_Wxlo);
    cudaGetSymbolAddress((void**)&whh, g_Whhi);
    cudaGetSymbolAddress((void**)&whl, g_Whlo);
    cudaGetSymbolAddress((void**)&ghh, g_Wghh);
    cudaGetSymbolAddress((void**)&ghl, g_Wghl);
    cudaGetSymbolAddress((void**)&gph, g_Wgph);
    cudaGetSymbolAddress((void**)&gpl, g_Wgpl);
    cudaGetSymbolAddress((void**)&wth, g_Wthi);
    cudaGetSymbolAddress((void**)&wtl, g_Wtlo);
    cudaGetSymbolAddress((void**)&xh,  g_xh);
    cudaGetSymbolAddress((void**)&xl,  g_xl);
    cudaGetSymbolAddress((void**)&hbh, g_hbh);
    cudaGetSymbolAddress((void**)&hbl, g_hbl);
    cudaGetSymbolAddress((void**)&hgh, g_hgh);
    cudaGetSymbolAddress((void**)&hgl, g_hgl);
    cudaGetSymbolAddress((void**)&ichi, g_ichi);
    cudaGetSymbolAddress((void**)&iclo, g_iclo);
    cudaGetSymbolAddress((void**)&cchi, g_cchi);
    cudaGetSymbolAddress((void**)&cclo, g_cclo);

    int devi = 0, nsm = 148, occ5 = 0, occc = 0;
    cudaGetDevice(&devi);
    cudaDeviceGetAttribute(&nsm, cudaDevAttrMultiProcessorCount, devi);
    cudaOccupancyMaxActiveBlocksPerMultiprocessor(&occ5, lstm5_mma, 128, 0);
    bool fused5 = ((long)occ5 * nsm >= 384);
    cudaOccupancyMaxActiveBlocksPerMultiprocessor(&occc, combsl<1>, 128, 0);
    bool fusedy = ((long)occc * nsm >= 320);

    conv_w_lstm<<<1024,256>>>(Wx, Wh, wxh, wxl, whh, whl);
    init_misc<<<1024,256>>>(Wg_h, Wg_p, ghh, ghl, gph, gpl,
                            x, xh, xl, c, hbh, hbl, hgh, hgl);
    conv_wilc<<<dim3(16,16,15),256>>>(Wilc, wth, wtl);

    for (int t=0; t<TT; t++){
        int p = t & 1, q = p ^ 1;
        const float* cp = c + (long)p*NLA*BH;
        float*       cq = c + (long)q*NLA*BH;
        const __nv_bfloat16* hbhp = hbh + (long)p*NLA*BH;
        __nv_bfloat16*       hbhq = hbh + (long)q*NLA*BH;
        const __nv_bfloat16* hblp = hbl + (long)p*NLA*BH;
        __nv_bfloat16*       hblq = hbl + (long)q*NLA*BH;
        const __nv_bfloat16* hghp = hgh + (long)p*BH;
        __nv_bfloat16*       hghq = hgh + (long)q*BH;
        const __nv_bfloat16* hglp = hgl + (long)p*BH;
        __nv_bfloat16*       hglq = hgl + (long)q*BH;

        if (fused5){
            lstm5_mma<<<dim3(32,4,3),128>>>(
                xh + (long)t*BH, xl + (long)t*BH,
                hbhp, hblp, hbhq, hblq,
                wxh, wxl, whh, whl,
                bl, cp, cq);
        } else {
            for (int l=0; l<5; l++){
                const __nv_bfloat16 *A1h_, *A1l_;
                long a1zs;
                if (l==0){ A1h_ = xh + (long)t*BH; A1l_ = xl + (long)t*BH; a1zs = 0; }
                else { A1h_ = hbhq + (long)(l-1)*3*BH; A1l_ = hblq + (long)(l-1)*3*BH; a1zs = BH; }
                lstm_mma<<<dim3(32,4,3),128>>>(
                    A1h_, A1l_, a1zs,
                    hbhp + (long)l*3*BH, hblp + (long)l*3*BH,
                    wxh + (long)l*4*HH, wxl + (long)l*4*HH,
                    whh + (long)l*4*HH, whl + (long)l*4*HH,
                    bl, l, cp + (long)l*3*BH,
                    cq + (long)l*3*BH,
                    hbhq + (long)l*3*BH, hblq + (long)l*3*BH);
            }
        }
        cell_mma<<<dim3(16,4,15),192>>>(
            hghp, hglp, hbhq, hblq,
            ghh, ghl, gph, gpl,
            bg, cq, ichi, iclo, cchi, cclo);
        t12_mma<<<dim3(16,4,15),128>>>(ichi, iclo, cchi, cclo, wth, wtl, tp);
        if (fusedy){
            combsl<1><<<dim3(8,8,5),128>>>(tp, bilc, Wsl, slp, bsl, hghq, hglq,
                                           Wlin + (long)t*HD, blin + t, out + (long)t*BSZ);
        } else {
            combsl<0><<<dim3(8,8,5),128>>>(tp, bilc, Wsl, slp, bsl, hghq, hglq,
                                           Wlin + (long)t*HD, blin + t, out + (long)t*BSZ);
            y_kernel<<<128,128>>>(slp, bsl, hghq, hglq, Wlin + (long)t*HD, blin + t, out + (long)t*BSZ);
        }
    }
}

// round 15
// speedup vs baseline: 1.7355x; 1.7248x over previous
#include <cuda_runtime.h>
#include <cuda_fp16.h>
#include <math.h>
#include <stdint.h>

#define TT 64
#define BSZ 128
#define HD 512
#define NLA 15
#define BH (BSZ*HD)
#define HH (HD*HD)
#define NWL (3L*5*4*512*512)
#define NWG (5L*3*3*512*512)

__device__ float g_c[2][NLA][BH];
__device__ float g_tp[30][BH];
__device__ float g_slp[5][BH];
__device__ volatile unsigned g_bar;
__device__ volatile unsigned g_bar2;

__device__ __half g_Wx16[NWL], g_Wh16[NWL];
__device__ __half g_Wgh16[NWG], g_Wgp16[NWG];
__device__ __half g_Wt16[15L*HH];
__device__ __half g_x16[(long)TT*BH];
__device__ __half g_h16[2][NLA][BH];
__device__ __half g_hg16[2][BH];
__device__ __half g_ic16[NLA][BH], g_cc16[NLA][BH];

__device__ __forceinline__ float sigf(float x){ return 1.0f/(1.0f+expf(-x)); }

__global__ void conv_w_lstm(const float* __restrict__ Wx, const float* __restrict__ Wh,
    __half* wx, __half* wh){
    for (long i = (long)blockIdx.x*blockDim.x+threadIdx.x; i < NWL;
         i += (long)gridDim.x*blockDim.x){
        wx[i] = __float2half(Wx[i]);
        wh[i] = __float2half(Wh[i]);
    }
}

// merged: conv Wg + conv x + zero state
__global__ void init_misc(const float* __restrict__ Gh, const float* __restrict__ Gp,
    __half* gh, __half* gp,
    const float* __restrict__ x, __half* x16,
    float* c0, __half* h0, __half* hg0){
    const long NX = (long)TT*BH;
    const long NZ = (long)NLA*BH;
    __half z = __float2half(0.f);
    for (long i = (long)blockIdx.x*blockDim.x+threadIdx.x; i < NWG;
         i += (long)gridDim.x*blockDim.x){
        gh[i] = __float2half(Gh[i]);
        gp[i] = __float2half(Gp[i]);
        if (i < NX) x16[i] = __float2half(x[i]);
        if (i < NZ){
            c0[i] = 0.f; h0[i] = z;
            if (i < BH) hg0[i] = z;
        }
    }
}

__global__ void conv_wilc(const float* __restrict__ W, __half* th){
    int zb = blockIdx.z;
    int z0 = blockIdx.y*32, y0 = blockIdx.x*32;
    __shared__ float s[32][33];
    int tx = threadIdx.x&31, ty = threadIdx.x>>5;
    const float* Wb = W + (long)zb*HH;
#pragma unroll
    for (int r=0;r<4;r++)
        s[ty+r*8][tx] = Wb[(long)(z0+ty+r*8)*512 + y0+tx];
    __syncthreads();
#pragma unroll
    for (int r=0;r<4;r++){
        long o = (long)zb*HH + (long)(y0+ty+r*8)*512 + z0+tx;
        th[o] = __float2half(s[tx][ty+r*8]);
    }
}

__device__ __forceinline__ void ldsm4(uint32_t addr, uint32_t &r0, uint32_t &r1,
                                      uint32_t &r2, uint32_t &r3){
    asm volatile("ldmatrix.sync.aligned.m8n8.x4.shared.b16 {%0,%1,%2,%3}, [%4];"
        : "=r"(r0),"=r"(r1),"=r"(r2),"=r"(r3) : "r"(addr));
}
__device__ __forceinline__ void mma16816(float* c, const uint32_t* a,
                                         uint32_t b0, uint32_t b1){
    asm volatile("mma.sync.aligned.m16n8k16.row.col.f32.f16.f16.f32 "
        "{%0,%1,%2,%3},{%4,%5,%6,%7},{%8,%9},{%0,%1,%2,%3};"
        : "+f"(c[0]),"+f"(c[1]),"+f"(c[2]),"+f"(c[3])
        : "r"(a[0]),"r"(a[1]),"r"(a[2]),"r"(a[3]),"r"(b0),"r"(b1));
}
__device__ __forceinline__ void cpa16(uint32_t dst, const void* src){
    asm volatile("cp.async.ca.shared.global [%0], [%1], 16;" :: "r"(dst), "l"(src));
}
__device__ __forceinline__ void cpa_commit(){ asm volatile("cp.async.commit_group;"); }

__device__ __forceinline__ void grid_barrier(volatile unsigned* bar, unsigned nblocks){
    __syncthreads();
    __threadfence();
    if (threadIdx.x == 0){
        unsigned token = atomicAdd((unsigned*)bar, 1u);
        unsigned target = (token/nblocks + 1u)*nblocks;
        while (*bar < target) { }
    }
    __syncthreads();
}

// ---- fused 5-level LSTM (fp16 single-pass), persistent, 384 blocks -----------
__global__ __launch_bounds__(128,3) void lstm5_mma(
    const __half* __restrict__ x_t,
    const __half* __restrict__ hp, __half* __restrict__ hq,
    const __half* __restrict__ wx, const __half* __restrict__ wh,
    const float* __restrict__ bl, const float* __restrict__ cpb,
    float* __restrict__ cqb)
{
    const int a = blockIdx.z;
    const int m0 = blockIdx.y*32, n0 = blockIdx.x*16;
    const int tid = threadIdx.x, lane = tid&31, g = tid>>5;

    __shared__ __align__(16) __half sA[3][32][40];
    __shared__ __align__(16) __half sW[3][4][16][40];

    const uint32_t sA_base = (uint32_t)__cvta_generic_to_shared(&sA[0][0][0]);
    const uint32_t sW_base = (uint32_t)__cvta_generic_to_shared(&sW[0][0][0][0]);

    const int a_row = lane&15, a_ko = (lane>>4)*8;
    const int b_r = lane&7, b_sel = lane>>3;
    const int b_rowoff = b_r + ((b_sel>>1)?8:0), b_ko = (b_sel&1)*8;

    for (int l=0; l<5; l++){
        const __half* Asrc[2];
        Asrc[0] = (l==0) ? x_t : (hq + (long)((l-1)*3+a)*BH);
        Asrc[1] = hp + (long)(l*3+a)*BH;
        const __half* Wsrc[2] = {wx + (long)(a*20+l*4)*HH, wh + (long)(a*20+l*4)*HH};

        float C[2][2][4];
#pragma unroll
        for (int mh=0;mh<2;mh++)
#pragma unroll
            for (int f=0;f<2;f++)
#pragma unroll
                for (int r=0;r<4;r++) C[mh][f][r]=0.f;

        auto prefetch = [&](int kc2){
            int st = kc2 % 3, s = kc2>>4, k0 = (kc2&15)*32;
            {
                int row = tid>>2, q = tid&3;
                cpa16(sA_base + (uint32_t)(((st*32 + row)*40 + q*8)*2),
                      Asrc[s] + (long)(m0+row)*512 + k0 + q*8);
            }
#pragma unroll
            for (int it=0; it<2; it++){
                int idx = tid + it*128;
                int q = idx&3, n = (idx>>2)&15, gg = (idx>>6)&3;
                cpa16(sW_base + (uint32_t)((((st*4+gg)*16 + n)*40 + q*8)*2),
                      Wsrc[s] + (long)gg*HH + (long)(n0+n)*512 + k0 + q*8);
            }
            cpa_commit();
        };

        prefetch(0); prefetch(1);
        for (int kc2=0; kc2<32; kc2++){
            const int st = kc2 % 3;
            if (kc2+2 < 32){
                prefetch(kc2+2);
                asm volatile("cp.async.wait_group 2;");
            } else if (kc2+1 < 32){
                asm volatile("cp.async.wait_group 1;");
            } else {
                asm volatile("cp.async.wait_group 0;");
            }
            __syncthreads();
#pragma unroll
            for (int kf=0;kf<2;kf++){
                uint32_t ah[2][4];
#pragma unroll
                for (int mh=0;mh<2;mh++){
                    uint32_t ad = sA_base + (uint32_t)(((st*32 + mh*16 + a_row)*40 + kf*16 + a_ko)*2);
                    ldsm4(ad, ah[mh][0], ah[mh][1], ah[mh][2], ah[mh][3]);
                }
                uint32_t b0,b1,b2,b3;
                {
                    uint32_t bd = sW_base + (uint32_t)((((st*4+g)*16 + b_rowoff)*40 + kf*16 + b_ko)*2);
                    ldsm4(bd, b0,b1,b2,b3);
                }
#pragma unroll
                for (int mh=0;mh<2;mh++){
                    mma16816(C[mh][0], ah[mh], b0, b1);
                    mma16816(C[mh][1], ah[mh], b2, b3);
                }
            }
            __syncthreads();
        }

        float* preS = (float*)&sW[0][0][0][0];
        {
            int r = lane>>2, i2 = (lane&3)*2;
#pragma unroll
            for (int mh=0;mh<2;mh++)
#pragma unroll
                for (int f=0;f<2;f++){
                    int col = f*8 + i2;
                    preS[(g*32 + mh*16 + r)*16 + col]     = C[mh][f][0];
                    preS[(g*32 + mh*16 + r)*16 + col+1]   = C[mh][f][1];
                    preS[(g*32 + mh*16 + r+8)*16 + col]   = C[mh][f][2];
                    preS[(g*32 + mh*16 + r+8)*16 + col+1] = C[mh][f][3];
                }
        }
        __syncthreads();
        {
            const float* cp = cpb + (long)(l*3+a)*BH;
            float* cq = cqb + (long)(l*3+a)*BH;
            __half* h_out = hq + (long)(l*3+a)*BH;
            for (int cell = tid; cell < 512; cell += 128){
                int m = cell>>4, n = cell&15;
                int gn = n0 + n;
                float p[4];
#pragma unroll
                for (int gg=0;gg<4;gg++)
                    p[gg] = preS[(gg*32+m)*16 + n] + bl[((long)(a*5+l)*4+gg)*512 + gn];
                long o = (long)(m0+m)*512 + gn;
                float cn = sigf(p[1])*cp[o] + sigf(p[0])*tanhf(p[2]);
                float hv = sigf(p[3])*tanhf(cn);
                cq[o] = cn;
                h_out[o] = __float2half(hv);
            }
        }
        if (l < 4) grid_barrier(&g_bar, 384u);
    }
}

// ---- single-level LSTM fallback (fp16) ---------------------------------------
__global__ __launch_bounds__(128) void lstm_mma(
    const __half* __restrict__ A1, long a1zs,
    const __half* __restrict__ A2,
    const __half* __restrict__ W1, const __half* __restrict__ W2,
    const float* __restrict__ bl, int l, const float* __restrict__ cpb,
    float* __restrict__ cqb, __half* __restrict__ hq)
{
    const int a = blockIdx.z;
    const int m0 = blockIdx.y*32, n0 = blockIdx.x*16;
    const int tid = threadIdx.x, lane = tid&31, g = tid>>5;

    __shared__ __align__(16) __half sA[3][32][40];
    __shared__ __align__(16) __half sW[3][4][16][40];

    const uint32_t sA_base = (uint32_t)__cvta_generic_to_shared(&sA[0][0][0]);
    const uint32_t sW_base = (uint32_t)__cvta_generic_to_shared(&sW[0][0][0][0]);

    const int a_row = lane&15, a_ko = (lane>>4)*8;
    const int b_r = lane&7, b_sel = lane>>3;
    const int b_rowoff = b_r + ((b_sel>>1)?8:0), b_ko = (b_sel&1)*8;

    const __half* Asrc[2] = {A1 + (long)a*a1zs, A2 + (long)a*BH};
    const __half* Wsrc[2] = {W1 + (long)a*20*HH, W2 + (long)a*20*HH};

    float C[2][2][4];
#pragma unroll
    for (int mh=0;mh<2;mh++)
#pragma unroll
        for (int f=0;f<2;f++)
#pragma unroll
            for (int r=0;r<4;r++) C[mh][f][r]=0.f;

    auto prefetch = [&](int kc2){
        int st = kc2 % 3, s = kc2>>4, k0 = (kc2&15)*32;
        {
            int row = tid>>2, q = tid&3;
            cpa16(sA_base + (uint32_t)(((st*32 + row)*40 + q*8)*2),
                  Asrc[s] + (long)(m0+row)*512 + k0 + q*8);
        }
#pragma unroll
        for (int it=0; it<2; it++){
            int idx = tid + it*128;
            int q = idx&3, n = (idx>>2)&15, gg = (idx>>6)&3;
            cpa16(sW_base + (uint32_t)((((st*4+gg)*16 + n)*40 + q*8)*2),
                  Wsrc[s] + (long)gg*HH + (long)(n0+n)*512 + k0 + q*8);
        }
        cpa_commit();
    };

    prefetch(0); prefetch(1);
    for (int kc2=0; kc2<32; kc2++){
        const int st = kc2 % 3;
        if (kc2+2 < 32){
            prefetch(kc2+2);
            asm volatile("cp.async.wait_group 2;");
        } else if (kc2+1 < 32){
            asm volatile("cp.async.wait_group 1;");
        } else {
            asm volatile("cp.async.wait_group 0;");
        }
        __syncthreads();
#pragma unroll
        for (int kf=0;kf<2;kf++){
            uint32_t ah[2][4];
#pragma unroll
            for (int mh=0;mh<2;mh++){
                uint32_t ad = sA_base + (uint32_t)(((st*32 + mh*16 + a_row)*40 + kf*16 + a_ko)*2);
                ldsm4(ad, ah[mh][0], ah[mh][1], ah[mh][2], ah[mh][3]);
            }
            uint32_t b0,b1,b2,b3;
            {
                uint32_t bd = sW_base + (uint32_t)((((st*4+g)*16 + b_rowoff)*40 + kf*16 + b_ko)*2);
                ldsm4(bd, b0,b1,b2,b3);
            }
#pragma unroll
            for (int mh=0;mh<2;mh++){
                mma16816(C[mh][0], ah[mh], b0, b1);
                mma16816(C[mh][1], ah[mh], b2, b3);
            }
        }
        __syncthreads();
    }

    float* preS = (float*)&sW[0][0][0][0];
    {
        int r = lane>>2, i2 = (lane&3)*2;
#pragma unroll
        for (int mh=0;mh<2;mh++)
#pragma unroll
            for (int f=0;f<2;f++){
                int col = f*8 + i2;
                preS[(g*32 + mh*16 + r)*16 + col]     = C[mh][f][0];
                preS[(g*32 + mh*16 + r)*16 + col+1]   = C[mh][f][1];
                preS[(g*32 + mh*16 + r+8)*16 + col]   = C[mh][f][2];
                preS[(g*32 + mh*16 + r+8)*16 + col+1] = C[mh][f][3];
            }
    }
    __syncthreads();
    {
        const float* cp = cpb + (long)a*BH;
        for (int cell = tid; cell < 512; cell += 128){
            int m = cell>>4, n = cell&15;
            int gn = n0 + n;
            float p[4];
#pragma unroll
            for (int gg=0;gg<4;gg++)
                p[gg] = preS[(gg*32+m)*16 + n] + bl[((long)(a*5+l)*4+gg)*512 + gn];
            long o = (long)a*BH + (long)(m0+m)*512 + gn;
            float cn = sigf(p[1])*cp[(long)(m0+m)*512+gn] + sigf(p[0])*tanhf(p[2]);
            float hv = sigf(p[3])*tanhf(cn);
            cqb[o] = cn;
            hq[o] = __float2half(hv);
        }
    }
}

// ---- cell block (fp16 single-pass), 2-stage ----------------------------------
__global__ __launch_bounds__(192) void cell_mma(
    const __half* __restrict__ Hg, const __half* __restrict__ Hb,
    const __half* __restrict__ Gh, const __half* __restrict__ Gp,
    const float* __restrict__ bg, const float* __restrict__ scb,
    __half* __restrict__ ic, __half* __restrict__ cc)
{
    const int zb = blockIdx.z;
    const int m0 = blockIdx.y*32, n0 = blockIdx.x*32;
    const int tid = threadIdx.x, lane = tid&31, wid = tid>>5;
    const int g = wid>>1, nb = (wid&1)*16;

    __shared__ __align__(16) __half sA[2][32][40];
    __shared__ __align__(16) __half sW[2][3][32][40];

    float C[2][2][4];
#pragma unroll
    for (int mh=0;mh<2;mh++)
#pragma unroll
        for (int f=0;f<2;f++)
#pragma unroll
            for (int r=0;r<4;r++) C[mh][f][r]=0.f;

    const __half* Asrc[2] = {Hg, Hb + (long)zb*BH};
    const __half* Wsrc[2] = {Gh + (long)zb*3*HH, Gp + (long)zb*3*HH};

    const uint32_t sA_base = (uint32_t)__cvta_generic_to_shared(&sA[0][0][0]);
    const uint32_t sW_base = (uint32_t)__cvta_generic_to_shared(&sW[0][0][0][0]);

    const int a_row = lane&15, a_ko = (lane>>4)*8;
    const int b_r = lane&7, b_sel = lane>>3;
    const int b_rowoff = b_r + ((b_sel>>1)?8:0), b_ko = (b_sel&1)*8;

    auto prefetch = [&](int kc2){
        int st = kc2&1, s = kc2>>4, k0 = (kc2&15)*32;
        if (tid < 128){
            int row = tid>>2, q = tid&3;
            cpa16(sA_base + (uint32_t)(((st*32 + row)*40 + q*8)*2),
                  Asrc[s] + (long)(m0+row)*512 + k0 + q*8);
        }
#pragma unroll
        for (int it=0; it<2; it++){
            int idx = tid + it*192;
            if (idx < 384){
                int q = idx&3, n = (idx>>2)&31, gg = idx>>7;
                cpa16(sW_base + (uint32_t)((((st*3+gg)*32 + n)*40 + q*8)*2),
                      Wsrc[s] + (long)gg*HH + (long)(n0+n)*512 + k0 + q*8);
            }
        }
        cpa_commit();
    };

    prefetch(0);
    for (int kc2=0; kc2<32; kc2++){
        const int st = kc2&1;
        if (kc2+1 < 32){
            prefetch(kc2+1);
            asm volatile("cp.async.wait_group 1;");
        } else {
            asm volatile("cp.async.wait_group 0;");
        }
        __syncthreads();
#pragma unroll
        for (int kf=0;kf<2;kf++){
            uint32_t ah[2][4];
#pragma unroll
            for (int mh=0;mh<2;mh++){
                uint32_t ad = sA_base + (uint32_t)(((st*32 + mh*16 + a_row)*40 + kf*16 + a_ko)*2);
                ldsm4(ad, ah[mh][0], ah[mh][1], ah[mh][2], ah[mh][3]);
            }
            uint32_t b0,b1,b2,b3;
            {
                uint32_t bd = sW_base + (uint32_t)((((st*3+g)*32 + nb + b_rowoff)*40 + kf*16 + b_ko)*2);
                ldsm4(bd, b0,b1,b2,b3);
            }
#pragma unroll
            for (int mh=0;mh<2;mh++){
                mma16816(C[mh][0], ah[mh], b0, b1);
                mma16816(C[mh][1], ah[mh], b2, b3);
            }
        }
        __syncthreads();
    }

    float* preS = (float*)&sW[0][0][0][0];
    {
        int r = lane>>2, i2 = (lane&3)*2;
#pragma unroll
        for (int mh=0;mh<2;mh++)
#pragma unroll
            for (int f=0;f<2;f++){
                int col = nb + f*8 + i2;
                preS[(g*32 + mh*16 + r)*32 + col]     = C[mh][f][0];
                preS[(g*32 + mh*16 + r)*32 + col+1]   = C[mh][f][1];
                preS[(g*32 + mh*16 + r+8)*32 + col]   = C[mh][f][2];
                preS[(g*32 + mh*16 + r+8)*32 + col+1] = C[mh][f][3];
            }
    }
    __syncthreads();
    {
        const float* sc = scb + (long)zb*BH;
        for (int cell = tid; cell < 1024; cell += 192){
            int m = cell>>5, n = cell&31;
            int gn = n0 + n;
            float p[3];
#pragma unroll
            for (int gg=0;gg<3;gg++)
                p[gg] = preS[(gg*32+m)*32 + n] + bg[((long)zb*3+gg)*512 + gn];
            long r = (long)(m0+m)*512 + gn;
            float icv = sigf(p[0]) * sc[r];
            float ccv = sigf(p[1])*tanhf(p[2]) + icv;
            long o = (long)zb*BH + r;
            ic[o] = __float2half(icv);
            cc[o] = __float2half(ccv);
        }
    }
}

// ---- t12 (fp16 single-pass), dual stream shares W tile -----------------------
__global__ __launch_bounds__(128) void t12_mma(
    const __half* __restrict__ ic, const __half* __restrict__ cc,
    const __half* __restrict__ Wt, float* __restrict__ tp)
{
    const int zb = blockIdx.z;
    const int l = zb/3, a = zb%3;
    const int m0 = blockIdx.y*32, n0 = blockIdx.x*32;
    const int tid = threadIdx.x, lane = tid&31, wid = tid>>5;
    const int s = wid>>1, nb = (wid&1)*16;

    __shared__ __align__(16) __half sA[2][2][32][40];
    __shared__ __align__(16) __half sW[2][32][40];

    float C[2][2][4];
#pragma unroll
    for (int mh=0;mh<2;mh++)
#pragma unroll
        for (int f=0;f<2;f++)
#pragma unroll
            for (int r=0;r<4;r++) C[mh][f][r]=0.f;

    const __half* Asrc[2] = {ic + (long)zb*BH, cc + (long)zb*BH};
    const __half* Wsrc = Wt + (long)zb*HH;

    const uint32_t sA_base = (uint32_t)__cvta_generic_to_shared(&sA[0][0][0][0]);
    const uint32_t sW_base = (uint32_t)__cvta_generic_to_shared(&sW[0][0][0]);

    const int a_row = lane&15, a_ko = (lane>>4)*8;
    const int b_r = lane&7, b_sel = lane>>3;
    const int b_rowoff = b_r + ((b_sel>>1)?8:0), b_ko = (b_sel&1)*8;

    auto prefetch = [&](int kc){
        int st = kc&1, k0 = kc*32;
#pragma unroll
        for (int it=0; it<2; it++){
            int idx = tid + it*128;
            int q = idx&3, row = (idx>>2)&31, ss = idx>>7;
            cpa16(sA_base + (uint32_t)((((st*2+ss)*32 + row)*40 + q*8)*2),
                  Asrc[ss] + (long)(m0+row)*512 + k0 + q*8);
        }
        {
            int q = tid&3, row = (tid>>2)&31;
            cpa16(sW_base + (uint32_t)(((st*32 + row)*40 + q*8)*2),
                  Wsrc + (long)(n0+row)*512 + k0 + q*8);
        }
        cpa_commit();
    };

    prefetch(0);
    for (int kc=0; kc<16; kc++){
        const int st = kc&1;
        if (kc+1 < 16){
            prefetch(kc+1);
            asm volatile("cp.async.wait_group 1;");
        } else {
            asm volatile("cp.async.wait_group 0;");
        }
        __syncthreads();
#pragma unroll
        for (int kf=0;kf<2;kf++){
            uint32_t ah[2][4];
#pragma unroll
            for (int mh=0;mh<2;mh++){
                uint32_t ad = sA_base + (uint32_t)((((st*2+s)*32 + mh*16 + a_row)*40 + kf*16 + a_ko)*2);
                ldsm4(ad, ah[mh][0], ah[mh][1], ah[mh][2], ah[mh][3]);
            }
            uint32_t b0,b1,b2,b3;
            {
                uint32_t bd = sW_base + (uint32_t)(((st*32 + nb + b_rowoff)*40 + kf*16 + b_ko)*2);
                ldsm4(bd, b0,b1,b2,b3);
            }
#pragma unroll
            for (int mh=0;mh<2;mh++){
                mma16816(C[mh][0], ah[mh], b0, b1);
                mma16816(C[mh][1], ah[mh], b2, b3);
            }
        }
        __syncthreads();
    }

    float* tpo = tp + ((long)((2*l+s)*3+a))*BH;
    {
        int r = lane>>2, i2 = (lane&3)*2;
#pragma unroll
        for (int mh=0;mh<2;mh++)
#pragma unroll
            for (int f=0;f<2;f++){
                int row = m0 + mh*16 + r;
                int col = n0 + nb + f*8 + i2;
                tpo[(long)row*512 + col]       = C[mh][f][0];
                tpo[(long)row*512 + col+1]     = C[mh][f][1];
                tpo[(long)(row+8)*512 + col]   = C[mh][f][2];
                tpo[(long)(row+8)*512 + col+1] = C[mh][f][3];
            }
    }
}

// ---- comb + single_li + (persistent) y ---------------------------------------
template <int TAIL>
__global__ __launch_bounds__(128) void combsl(
    const float* __restrict__ tp, const float* __restrict__ bilc,
    const float* __restrict__ Wsl, float* __restrict__ part,
    const float* __restrict__ bsl, __half* __restrict__ hg,
    const float* __restrict__ wlin_t, const float* __restrict__ blin_t,
    float* __restrict__ outp)
{
    const int l = blockIdx.z, m0 = blockIdx.y*16, n0 = blockIdx.x*64;
    __shared__ __align__(16) float s1[16][520];
    __shared__ __align__(16) float Ws[16][68];
    const int tid = threadIdx.x;
    const int row = tid>>3, ln = tid&7;
    const int b = m0 + row;

    float mx = -1e30f;
    for (int i=0;i<64;i++){
        int z = ln + i*8;
        float v1 = bilc[(long)(l*3+0)*512+z] + bilc[(long)(l*3+1)*512+z] + bilc[(long)(l*3+2)*512+z];
#pragma unroll
        for (int a=0;a<3;a++)
            v1 += tp[((long)((2*l+0)*3+a))*BH + (long)b*512 + z];
        s1[row][z] = v1;
        mx = fmaxf(mx, v1);
    }
#pragma unroll
    for (int o=4;o>0;o>>=1) mx = fmaxf(mx, __shfl_xor_sync(0xffffffffu, mx, o, 8));
    float sm = 0.f;
    for (int i=0;i<64;i++){
        int z = ln + i*8;
        float e = expf(s1[row][z] - mx);
        s1[row][z] = e; sm += e;
    }
#pragma unroll
    for (int o=4;o>0;o>>=1) sm += __shfl_xor_sync(0xffffffffu, sm, o, 8);
    float inv = 1.f/sm;
    for (int i=0;i<64;i++){
        int z = ln + i*8;
        float v2 = bilc[(long)(l*3+0)*512+z] + bilc[(long)(l*3+1)*512+z] + bilc[(long)(l*3+2)*512+z];
#pragma unroll
        for (int a=0;a<3;a++)
            v2 += tp[((long)((2*l+1)*3+a))*BH + (long)b*512 + z];
        s1[row][z] = s1[row][z] * inv * sigf(v2);
    }
    __syncthreads();

    const int tx = tid&15, ty = tid>>4;
    const int wlm = tid>>1, wlk = (tid&1)<<3;
    float acc[2][4];
#pragma unroll
    for (int i=0;i<2;i++)
#pragma unroll
        for (int j=0;j<4;j++) acc[i][j]=0.f;
    for (int k0=0;k0<512;k0+=16){
        const float* wp = Wsl + (long)(n0+wlm)*2560 + l*512 + k0+wlk;
        float4 u0=*(const float4*)wp, u1=*(const float4*)(wp+4);
        Ws[wlk][wlm]=u0.x; Ws[wlk+1][wlm]=u0.y; Ws[wlk+2][wlm]=u0.z; Ws[wlk+3][wlm]=u0.w;
        Ws[wlk+4][wlm]=u1.x; Ws[wlk+5][wlm]=u1.y; Ws[wlk+6][wlm]=u1.z; Ws[wlk+7][wlm]=u1.w;
        __syncthreads();
#pragma unroll
        for (int kk=0;kk<16;kk++){
            float a0 = s1[ty*2][k0+kk], a1 = s1[ty*2+1][k0+kk];
            float4 w = *(const float4*)&Ws[kk][tx*4];
            acc[0][0]+=a0*w.x; acc[0][1]+=a0*w.y; acc[0][2]+=a0*w.z; acc[0][3]+=a0*w.w;
            acc[1][0]+=a1*w.x; acc[1][1]+=a1*w.y; acc[1][2]+=a1*w.z; acc[1][3]+=a1*w.w;
        }
        __syncthreads();
    }
#pragma unroll
    for (int i=0;i<2;i++)
#pragma unroll
        for (int j=0;j<4;j++)
            part[(long)l*BH + (long)(m0+ty*2+i)*512 + n0+tx*4+j] = acc[i][j];

    if (TAIL){
        grid_barrier(&g_bar2, 320u);
        int fid = blockIdx.x + (blockIdx.y<<3) + (blockIdx.z<<6);
        if (fid < 128){
            int bb = fid;
            float s = 0.f;
            for (int j=tid; j<512; j+=128){
                long idx = (long)bb*512 + j;
                float h = bsl[j] + part[idx] + part[BH+idx] + part[2L*BH+idx]
                        + part[3L*BH+idx] + part[4L*BH+idx];
                hg[idx] = __float2half(h);
                s += h * wlin_t[j];
            }
            float* red = &s1[0][0];
            red[tid]=s; __syncthreads();
            for (int st=64; st>0; st>>=1){ if (tid<st) red[tid]+=red[tid+st]; __syncthreads(); }
            if (tid==0) outp[bb] = red[0] + blin_t[0];
        }
    }
}

__global__ void y_kernel(const float* __restrict__ part, const float* __restrict__ bsl,
                         __half* __restrict__ hg, const float* __restrict__ wlin_t,
                         const float* __restrict__ blin_t, float* __restrict__ outp)
{
    int b = blockIdx.x, tid = threadIdx.x;
    float s = 0.f;
    for (int j=tid; j<512; j+=128){
        long idx = (long)b*512 + j;
        float h = bsl[j] + part[idx] + part[BH+idx] + part[2L*BH+idx]
                + part[3L*BH+idx] + part[4L*BH+idx];
        hg[idx] = __float2half(h);
        s += h * wlin_t[j];
    }
    __shared__ float red[128];
    red[tid]=s; __syncthreads();
    for (int st=64; st>0; st>>=1){ if (tid<st) red[tid]+=red[tid+st]; __syncthreads(); }
    if (tid==0) outp[b] = red[0] + blin_t[0];
}

extern "C" void kernel_launch(void* const* d_in, const int* in_sizes, int n_in,
                              void* d_out, int out_size)
{
    const float* x     = (const float*)d_in[0];
    const float* Wx    = (const float*)d_in[1];
    const float* Wh    = (const float*)d_in[2];
    const float* bl    = (const float*)d_in[3];
    const float* Wg_h  = (const float*)d_in[4];
    const float* Wg_p  = (const float*)d_in[5];
    const float* bg    = (const float*)d_in[6];
    const float* Wilc  = (const float*)d_in[7];
    const float* bilc  = (const float*)d_in[8];
    const float* Wsl   = (const float*)d_in[9];
    const float* bsl   = (const float*)d_in[10];
    const float* Wlin  = (const float*)d_in[11];
    const float* blin  = (const float*)d_in[12];
    float* out = (float*)d_out;

    float *c, *tp, *slp;
    __half *wx16, *wh16, *gh16, *gp16, *wt16, *x16, *h16, *hg16, *ic16, *cc16;
    cudaGetSymbolAddress((void**)&c,    g_c);
    cudaGetSymbolAddress((void**)&tp,   g_tp);
    cudaGetSymbolAddress((void**)&slp,  g_slp);
    cudaGetSymbolAddress((void**)&wx16, g_Wx16);
    cudaGetSymbolAddress((void**)&wh16, g_Wh16);
    cudaGetSymbolAddress((void**)&gh16, g_Wgh16);
    cudaGetSymbolAddress((void**)&gp16, g_Wgp16);
    cudaGetSymbolAddress((void**)&wt16, g_Wt16);
    cudaGetSymbolAddress((void**)&x16,  g_x16);
    cudaGetSymbolAddress((void**)&h16,  g_h16);
    cudaGetSymbolAddress((void**)&hg16, g_hg16);
    cudaGetSymbolAddress((void**)&ic16, g_ic16);
    cudaGetSymbolAddress((void**)&cc16, g_cc16);

    int devi = 0, nsm = 148, occ5 = 0, occc = 0;
    cudaGetDevice(&devi);
    cudaDeviceGetAttribute(&nsm, cudaDevAttrMultiProcessorCount, devi);
    cudaOccupancyMaxActiveBlocksPerMultiprocessor(&occ5, lstm5_mma, 128, 0);
    bool fused5 = ((long)occ5 * nsm >= 384);
    cudaOccupancyMaxActiveBlocksPerMultiprocessor(&occc, combsl<1>, 128, 0);
    bool fusedy = ((long)occc * nsm >= 320);

    conv_w_lstm<<<1024,256>>>(Wx, Wh, wx16, wh16);
    init_misc<<<1024,256>>>(Wg_h, Wg_p, gh16, gp16, x, x16, c, h16, hg16);
    conv_wilc<<<dim3(16,16,15),256>>>(Wilc, wt16);

    for (int t=0; t<TT; t++){
        int p = t & 1, q = p ^ 1;
        const float* cp = c + (long)p*NLA*BH;
        float*       cq = c + (long)q*NLA*BH;
        const __half* hp = h16 + (long)p*NLA*BH;
        __half*       hq = h16 + (long)q*NLA*BH;
        const __half* hgp = hg16 + (long)p*BH;
        __half*       hgq = hg16 + (long)q*BH;

        if (fused5){
            lstm5_mma<<<dim3(32,4,3),128>>>(
                x16 + (long)t*BH, hp, hq, wx16, wh16, bl, cp, cq);
        } else {
            for (int l=0; l<5; l++){
                const __half* A1 = (l==0) ? (x16 + (long)t*BH) : (hq + (long)(l-1)*3*BH);
                long a1zs = (l==0) ? 0 : BH;
                lstm_mma<<<dim3(32,4,3),128>>>(
                    A1, a1zs, hp + (long)l*3*BH,
                    wx16 + (long)l*4*HH, wh16 + (long)l*4*HH,
                    bl, l, cp + (long)l*3*BH,
                    cq + (long)l*3*BH, hq + (long)l*3*BH);
            }
        }
        cell_mma<<<dim3(16,4,15),192>>>(
            hgp, hq, gh16, gp16, bg, cq, ic16, cc16);
        t12_mma<<<dim3(16,4,15),128>>>(ic16, cc16, wt16, tp);
        if (fusedy){
            combsl<1><<<dim3(8,8,5),128>>>(tp, bilc, Wsl, slp, bsl, hgq,
                                           Wlin + (long)t*HD, blin + t, out + (long)t*BSZ);
        } else {
            combsl<0><<<dim3(8,8,5),128>>>(tp, bilc, Wsl, slp, bsl, hgq,
                                           Wlin + (long)t*HD, blin + t, out + (long)t*BSZ);
            y_kernel<<<128,128>>>(slp, bsl, hgq, Wlin + (long)t*HD, blin + t, out + (long)t*BSZ);
        }
    }
}